// round 1
// baseline (speedup 1.0000x reference)
#include <cuda_runtime.h>
#include <math.h>

#define S_LEN    4096
#define D_MODEL  1024
#define QKV_COLS 3072
#define N_HEADS  16
#define HEAD_DIM 64
#define ATT_SCALE 0.125f   // 1/sqrt(64)

// Scratch (no cudaMalloc allowed): qkv activations + attention output
static __device__ float g_qkv[S_LEN * QKV_COLS];    // [S, 3*D]
static __device__ float g_attn[S_LEN * D_MODEL];    // [S, D]

// ---------------------------------------------------------------------------
// SGEMM: C[M,N] = A[M,K] @ B[K,N] + bias[N]
// 128x128 block, BK=8, 256 threads, 8x8 per-thread tile.
// M % 128 == 0, N % 128 == 0, K % 8 == 0 (true for all our shapes).
// ---------------------------------------------------------------------------
__global__ __launch_bounds__(256)
void gemm_bias_kernel(const float* __restrict__ A, const float* __restrict__ B,
                      const float* __restrict__ bias, float* __restrict__ C,
                      int M, int N, int K)
{
    const int BM = 128, BN = 128, BK = 8;
    __shared__ float As[BK][BM];
    __shared__ float Bs[BK][BN];

    const int tid = threadIdx.x;
    const int bx = blockIdx.x, by = blockIdx.y;
    const int ty = tid >> 4;          // 0..15
    const int tx = tid & 15;          // 0..15

    const int rowA = tid >> 1;        // 0..127
    const int colA = (tid & 1) << 2;  // 0 or 4
    const int rowB = tid >> 5;        // 0..7
    const int colB = (tid & 31) << 2; // 0..124

    const float* Ab = A + (size_t)(by * BM) * K;
    const float* Bb = B + (size_t)(bx * BN);

    float acc[8][8];
#pragma unroll
    for (int i = 0; i < 8; i++)
#pragma unroll
        for (int j = 0; j < 8; j++) acc[i][j] = 0.f;

    for (int k0 = 0; k0 < K; k0 += BK) {
        float4 a4 = *(const float4*)(Ab + (size_t)rowA * K + k0 + colA);
        As[colA + 0][rowA] = a4.x;
        As[colA + 1][rowA] = a4.y;
        As[colA + 2][rowA] = a4.z;
        As[colA + 3][rowA] = a4.w;
        *(float4*)&Bs[rowB][colB] =
            *(const float4*)(Bb + (size_t)(k0 + rowB) * N + colB);
        __syncthreads();

#pragma unroll
        for (int kk = 0; kk < BK; kk++) {
            float rm[8], rn[8];
            *(float4*)(rm)     = *(float4*)&As[kk][ty * 8];
            *(float4*)(rm + 4) = *(float4*)&As[kk][ty * 8 + 4];
            *(float4*)(rn)     = *(float4*)&Bs[kk][tx * 8];
            *(float4*)(rn + 4) = *(float4*)&Bs[kk][tx * 8 + 4];
#pragma unroll
            for (int i = 0; i < 8; i++)
#pragma unroll
                for (int j = 0; j < 8; j++)
                    acc[i][j] += rm[i] * rn[j];
        }
        __syncthreads();
    }

    const int colBase = bx * BN + tx * 8;
    float bv[8];
#pragma unroll
    for (int j = 0; j < 8; j++) bv[j] = bias[colBase + j];

#pragma unroll
    for (int i = 0; i < 8; i++) {
        const size_t row = (size_t)(by * BM + ty * 8 + i);
        float4 r0, r1;
        r0.x = acc[i][0] + bv[0]; r0.y = acc[i][1] + bv[1];
        r0.z = acc[i][2] + bv[2]; r0.w = acc[i][3] + bv[3];
        r1.x = acc[i][4] + bv[4]; r1.y = acc[i][5] + bv[5];
        r1.z = acc[i][6] + bv[6]; r1.w = acc[i][7] + bv[7];
        *(float4*)&C[row * N + colBase]     = r0;
        *(float4*)&C[row * N + colBase + 4] = r1;
    }
}

// ---------------------------------------------------------------------------
// Flash attention, fp32, causal.
// Grid: (S/64, N_HEADS). Block: 256 threads.
// Each thread: 4 q-rows (a*4..) x 4 keys / 4 out-cols (b*4..).
// qkv layout per row (3072): [Q 0..1023 | K 1024..2047 | V 2048..3071],
// head h occupies cols h*64..h*64+63 within each third.
// ---------------------------------------------------------------------------
#define FPAD 68  // floats per smem row (64 data + 4 pad, keeps 16B alignment)

__global__ __launch_bounds__(256)
void flash_attn_kernel(const float* __restrict__ qkv, float* __restrict__ out)
{
    extern __shared__ float sm[];
    float* Qs = sm;                  // 64 * FPAD
    float* Ks = Qs + 64 * FPAD;
    float* Vs = Ks + 64 * FPAD;
    float* Ps = Vs + 64 * FPAD;

    const int qt  = blockIdx.x;      // q tile 0..63
    const int h   = blockIdx.y;      // head
    const int tid = threadIdx.x;
    const int a = tid >> 4;          // 0..15 -> q rows a*4..a*4+3
    const int b = tid & 15;          // 0..15 -> keys/out cols b*4..b*4+3
    const int q0 = qt * 64;

    const float* Qg = qkv + (size_t)q0 * QKV_COLS + h * HEAD_DIM;

    // Load Q tile (64x64)
    for (int i = tid; i < 64 * 16; i += 256) {
        const int r = i >> 4, c = (i & 15) << 2;
        *(float4*)&Qs[r * FPAD + c] =
            *(const float4*)(Qg + (size_t)r * QKV_COLS + c);
    }

    float m[4], l[4], o[4][4];
#pragma unroll
    for (int i = 0; i < 4; i++) {
        m[i] = -1e30f; l[i] = 0.f;
#pragma unroll
        for (int c = 0; c < 4; c++) o[i][c] = 0.f;
    }
    __syncthreads();

    for (int kt = 0; kt <= qt; kt++) {
        const int k0 = kt * 64;
        const float* Kg = qkv + (size_t)k0 * QKV_COLS + D_MODEL     + h * HEAD_DIM;
        const float* Vg = qkv + (size_t)k0 * QKV_COLS + 2 * D_MODEL + h * HEAD_DIM;

        for (int i = tid; i < 64 * 16; i += 256) {
            const int r = i >> 4, c = (i & 15) << 2;
            *(float4*)&Ks[r * FPAD + c] =
                *(const float4*)(Kg + (size_t)r * QKV_COLS + c);
            *(float4*)&Vs[r * FPAD + c] =
                *(const float4*)(Vg + (size_t)r * QKV_COLS + c);
        }
        __syncthreads();

        // --- scores: s[i][j] = q(a*4+i) . k(b*4+j) ---
        float s[4][4];
#pragma unroll
        for (int i = 0; i < 4; i++)
#pragma unroll
            for (int j = 0; j < 4; j++) s[i][j] = 0.f;

        for (int d0 = 0; d0 < 64; d0 += 4) {
            float4 qv[4], kv[4];
#pragma unroll
            for (int i = 0; i < 4; i++)
                qv[i] = *(float4*)&Qs[(a * 4 + i) * FPAD + d0];
#pragma unroll
            for (int j = 0; j < 4; j++)
                kv[j] = *(float4*)&Ks[(b * 4 + j) * FPAD + d0];
#pragma unroll
            for (int i = 0; i < 4; i++)
#pragma unroll
                for (int j = 0; j < 4; j++)
                    s[i][j] += qv[i].x * kv[j].x + qv[i].y * kv[j].y +
                               qv[i].z * kv[j].z + qv[i].w * kv[j].w;
        }

        // scale + causal mask (only the diagonal tile needs masking)
        if (kt == qt) {
#pragma unroll
            for (int i = 0; i < 4; i++)
#pragma unroll
                for (int j = 0; j < 4; j++) {
                    const int gq = a * 4 + i, gk = b * 4 + j;
                    s[i][j] = (gk <= gq) ? s[i][j] * ATT_SCALE : -1e30f;
                }
        } else {
#pragma unroll
            for (int i = 0; i < 4; i++)
#pragma unroll
                for (int j = 0; j < 4; j++) s[i][j] *= ATT_SCALE;
        }

        // --- online softmax ---
        float rmax[4];
#pragma unroll
        for (int i = 0; i < 4; i++)
            rmax[i] = fmaxf(fmaxf(s[i][0], s[i][1]), fmaxf(s[i][2], s[i][3]));
#pragma unroll
        for (int off = 1; off < 16; off <<= 1)
#pragma unroll
            for (int i = 0; i < 4; i++)
                rmax[i] = fmaxf(rmax[i], __shfl_xor_sync(0xffffffffu, rmax[i], off));

        float alpha[4];
#pragma unroll
        for (int i = 0; i < 4; i++) {
            const float mn = fmaxf(m[i], rmax[i]);
            alpha[i] = __expf(m[i] - mn);
            m[i] = mn;
        }

        float rsum[4];
#pragma unroll
        for (int i = 0; i < 4; i++) rsum[i] = 0.f;
#pragma unroll
        for (int i = 0; i < 4; i++)
#pragma unroll
            for (int j = 0; j < 4; j++) {
                const float p = __expf(s[i][j] - m[i]);
                s[i][j] = p;
                rsum[i] += p;
            }
#pragma unroll
        for (int off = 1; off < 16; off <<= 1)
#pragma unroll
            for (int i = 0; i < 4; i++)
                rsum[i] += __shfl_xor_sync(0xffffffffu, rsum[i], off);

#pragma unroll
        for (int i = 0; i < 4; i++) {
            l[i] = l[i] * alpha[i] + rsum[i];
#pragma unroll
            for (int c = 0; c < 4; c++) o[i][c] *= alpha[i];
        }

        // store P to smem
#pragma unroll
        for (int i = 0; i < 4; i++) {
            float4 p4 = make_float4(s[i][0], s[i][1], s[i][2], s[i][3]);
            *(float4*)&Ps[(a * 4 + i) * FPAD + b * 4] = p4;
        }
        __syncthreads();

        // --- O += P @ V ---
        for (int k4 = 0; k4 < 64; k4 += 4) {
            float4 p4[4], v4[4];
#pragma unroll
            for (int i = 0; i < 4; i++)
                p4[i] = *(float4*)&Ps[(a * 4 + i) * FPAD + k4];
#pragma unroll
            for (int kk = 0; kk < 4; kk++)
                v4[kk] = *(float4*)&Vs[(k4 + kk) * FPAD + b * 4];
#pragma unroll
            for (int i = 0; i < 4; i++) {
                o[i][0] += p4[i].x * v4[0].x + p4[i].y * v4[1].x +
                           p4[i].z * v4[2].x + p4[i].w * v4[3].x;
                o[i][1] += p4[i].x * v4[0].y + p4[i].y * v4[1].y +
                           p4[i].z * v4[2].y + p4[i].w * v4[3].y;
                o[i][2] += p4[i].x * v4[0].z + p4[i].y * v4[1].z +
                           p4[i].z * v4[2].z + p4[i].w * v4[3].z;
                o[i][3] += p4[i].x * v4[0].w + p4[i].y * v4[1].w +
                           p4[i].z * v4[2].w + p4[i].w * v4[3].w;
            }
        }
        __syncthreads();
    }

    // write O / l to g_attn [S, D]: col = h*64 + b*4 + c
#pragma unroll
    for (int i = 0; i < 4; i++) {
        const float inv = 1.f / l[i];
        const size_t row = (size_t)(q0 + a * 4 + i);
        float4 r;
        r.x = o[i][0] * inv; r.y = o[i][1] * inv;
        r.z = o[i][2] * inv; r.w = o[i][3] * inv;
        *(float4*)&out[row * D_MODEL + h * HEAD_DIM + b * 4] = r;
    }
}

// ---------------------------------------------------------------------------
extern "C" void kernel_launch(void* const* d_in, const int* in_sizes, int n_in,
                              void* d_out, int out_size)
{
    const float* x     = (const float*)d_in[0];
    const float* w_qkv = (const float*)d_in[1];
    const float* b_qkv = (const float*)d_in[2];
    const float* w_out = (const float*)d_in[3];
    const float* b_out = (const float*)d_in[4];
    float* out = (float*)d_out;

    float *qkv, *attn;
    cudaGetSymbolAddress((void**)&qkv, g_qkv);
    cudaGetSymbolAddress((void**)&attn, g_attn);

    const int flash_smem = 4 * 64 * FPAD * (int)sizeof(float);  // 69632 B
    cudaFuncSetAttribute(flash_attn_kernel,
                         cudaFuncAttributeMaxDynamicSharedMemorySize, flash_smem);

    // 1) qkv = x @ w_qkv + b_qkv   [4096,1024]x[1024,3072]
    {
        dim3 grid(QKV_COLS / 128, S_LEN / 128);
        gemm_bias_kernel<<<grid, 256>>>(x, w_qkv, b_qkv, qkv,
                                        S_LEN, QKV_COLS, D_MODEL);
    }

    // 2) causal flash attention -> attn [4096,1024]
    {
        dim3 grid(S_LEN / 64, N_HEADS);
        flash_attn_kernel<<<grid, 256, flash_smem>>>(qkv, attn);
    }

    // 3) out = attn @ w_out + b_out  [4096,1024]x[1024,1024]
    {
        dim3 grid(D_MODEL / 128, S_LEN / 128);
        gemm_bias_kernel<<<grid, 256>>>(attn, w_out, b_out, out,
                                        S_LEN, D_MODEL, D_MODEL);
    }
}

// round 2
// speedup vs baseline: 1.5231x; 1.5231x over previous
#include <cuda_runtime.h>
#include <math.h>

#define S_LEN    4096
#define D_MODEL  1024
#define QKV_COLS 3072
#define N_HEADS  16
#define HEAD_DIM 64
#define ATT_SCALE 0.125f   // 1/sqrt(64)

// Scratch (no cudaMalloc allowed)
static __device__ float g_qkv[S_LEN * QKV_COLS];    // [S, 3*D]
static __device__ float g_attn[S_LEN * D_MODEL];    // [S, D]

// ---------------------------------------------------------------------------
// SGEMM: C[M,N] = A[M,K] @ B[K,N] + bias[N]   (unchanged from R1)
// ---------------------------------------------------------------------------
__global__ __launch_bounds__(256)
void gemm_bias_kernel(const float* __restrict__ A, const float* __restrict__ B,
                      const float* __restrict__ bias, float* __restrict__ C,
                      int M, int N, int K)
{
    const int BM = 128, BN = 128, BK = 8;
    __shared__ float As[BK][BM];
    __shared__ float Bs[BK][BN];

    const int tid = threadIdx.x;
    const int bx = blockIdx.x, by = blockIdx.y;
    const int ty = tid >> 4;
    const int tx = tid & 15;

    const int rowA = tid >> 1;
    const int colA = (tid & 1) << 2;
    const int rowB = tid >> 5;
    const int colB = (tid & 31) << 2;

    const float* Ab = A + (size_t)(by * BM) * K;
    const float* Bb = B + (size_t)(bx * BN);

    float acc[8][8];
#pragma unroll
    for (int i = 0; i < 8; i++)
#pragma unroll
        for (int j = 0; j < 8; j++) acc[i][j] = 0.f;

    for (int k0 = 0; k0 < K; k0 += BK) {
        float4 a4 = *(const float4*)(Ab + (size_t)rowA * K + k0 + colA);
        As[colA + 0][rowA] = a4.x;
        As[colA + 1][rowA] = a4.y;
        As[colA + 2][rowA] = a4.z;
        As[colA + 3][rowA] = a4.w;
        *(float4*)&Bs[rowB][colB] =
            *(const float4*)(Bb + (size_t)(k0 + rowB) * N + colB);
        __syncthreads();

#pragma unroll
        for (int kk = 0; kk < BK; kk++) {
            float rm[8], rn[8];
            *(float4*)(rm)     = *(float4*)&As[kk][ty * 8];
            *(float4*)(rm + 4) = *(float4*)&As[kk][ty * 8 + 4];
            *(float4*)(rn)     = *(float4*)&Bs[kk][tx * 8];
            *(float4*)(rn + 4) = *(float4*)&Bs[kk][tx * 8 + 4];
#pragma unroll
            for (int i = 0; i < 8; i++)
#pragma unroll
                for (int j = 0; j < 8; j++)
                    acc[i][j] += rm[i] * rn[j];
        }
        __syncthreads();
    }

    const int colBase = bx * BN + tx * 8;
    float bv[8];
#pragma unroll
    for (int j = 0; j < 8; j++) bv[j] = bias[colBase + j];

#pragma unroll
    for (int i = 0; i < 8; i++) {
        const size_t row = (size_t)(by * BM + ty * 8 + i);
        float4 r0, r1;
        r0.x = acc[i][0] + bv[0]; r0.y = acc[i][1] + bv[1];
        r0.z = acc[i][2] + bv[2]; r0.w = acc[i][3] + bv[3];
        r1.x = acc[i][4] + bv[4]; r1.y = acc[i][5] + bv[5];
        r1.z = acc[i][6] + bv[6]; r1.w = acc[i][7] + bv[7];
        *(float4*)&C[row * N + colBase]     = r0;
        *(float4*)&C[row * N + colBase + 4] = r1;
    }
}

// ---------------------------------------------------------------------------
// Flash attention v2: outer-product structure.
// Block: 256 threads. Grid: (32 q-blocks of 128 rows, 16 heads).
// Tiles: 128 q-rows x 128 keys per iteration.
// QK^T: Qt[d][q], Kt[d][k] transposed in smem -> per-thread 8x8 outer product,
//       1 B LDS per FMA. PV: Ps[q][k] row-major, per-thread 8x4, 1.5 B/FMA.
// smem: Qt 32K + Kt 32K + Vs 32K + Ps 64K = 160 KB (1 block/SM).
// ---------------------------------------------------------------------------
__global__ __launch_bounds__(256, 1)
void flash_attn_kernel(const float* __restrict__ qkv, float* __restrict__ out)
{
    extern __shared__ float sm[];
    float* Qt = sm;                   // [64][128]  Qt[d][q]
    float* Kt = Qt + 64 * 128;        // [64][128]  Kt[d][k]
    float* Vs = Kt + 64 * 128;        // [128][64]  Vs[k][c]
    float* Ps = Vs + 128 * 64;        // [128][128] Ps[q][k]

    const int qb  = blockIdx.x;       // q block 0..31
    const int h   = blockIdx.y;
    const int tid = threadIdx.x;
    const int ty  = tid >> 4;         // 0..15 -> q rows ty*8..+7
    const int tx  = tid & 15;         // 0..15 -> keys tx*8..+7 / out cols tx*4..+3
    const int q0  = qb * 128;

    // ---- load Q tile transposed: Qt[d][q] ----
    {
        const float* Qg = qkv + (size_t)q0 * QKV_COLS + h * HEAD_DIM;
        const int r = tid >> 1;           // 0..127
        const int b = tid & 1;
#pragma unroll
        for (int p = 0; p < 8; p++) {
            const int c = (b + 2 * p) << 2;   // 0..60
            float4 v = *(const float4*)(Qg + (size_t)r * QKV_COLS + c);
            Qt[(c + 0) * 128 + r] = v.x;
            Qt[(c + 1) * 128 + r] = v.y;
            Qt[(c + 2) * 128 + r] = v.z;
            Qt[(c + 3) * 128 + r] = v.w;
        }
    }

    float m[8], l[8], o[8][4];
#pragma unroll
    for (int i = 0; i < 8; i++) {
        m[i] = -1e30f; l[i] = 0.f;
#pragma unroll
        for (int c = 0; c < 4; c++) o[i][c] = 0.f;
    }

    for (int kt = 0; kt <= qb; kt++) {
        const int k0 = kt * 128;
        const float* Kg = qkv + (size_t)k0 * QKV_COLS + D_MODEL     + h * HEAD_DIM;
        const float* Vg = qkv + (size_t)k0 * QKV_COLS + 2 * D_MODEL + h * HEAD_DIM;

        __syncthreads();   // prev PV done (and Q visible on first iter)

        // ---- load K transposed ----
        {
            const int r = tid >> 1;
            const int b = tid & 1;
#pragma unroll
            for (int p = 0; p < 8; p++) {
                const int c = (b + 2 * p) << 2;
                float4 v = *(const float4*)(Kg + (size_t)r * QKV_COLS + c);
                Kt[(c + 0) * 128 + r] = v.x;
                Kt[(c + 1) * 128 + r] = v.y;
                Kt[(c + 2) * 128 + r] = v.z;
                Kt[(c + 3) * 128 + r] = v.w;
            }
        }
        // ---- load V row-major ----
#pragma unroll
        for (int i = 0; i < 8; i++) {
            const int idx = tid + i * 256;          // 0..2047
            const int r = idx >> 4, c = (idx & 15) << 2;
            *(float4*)&Vs[r * 64 + c] =
                *(const float4*)(Vg + (size_t)r * QKV_COLS + c);
        }
        __syncthreads();

        // ---- scores: s = Q @ K^T (outer product over d) ----
        float s[8][8];
#pragma unroll
        for (int i = 0; i < 8; i++)
#pragma unroll
            for (int j = 0; j < 8; j++) s[i][j] = 0.f;

#pragma unroll 4
        for (int d = 0; d < 64; d++) {
            float rm[8], rn[8];
            *(float4*)(rm)     = *(float4*)&Qt[d * 128 + ty * 8];
            *(float4*)(rm + 4) = *(float4*)&Qt[d * 128 + ty * 8 + 4];
            *(float4*)(rn)     = *(float4*)&Kt[d * 128 + tx * 8];
            *(float4*)(rn + 4) = *(float4*)&Kt[d * 128 + tx * 8 + 4];
#pragma unroll
            for (int i = 0; i < 8; i++)
#pragma unroll
                for (int j = 0; j < 8; j++)
                    s[i][j] += rm[i] * rn[j];
        }

        // ---- scale + causal mask (only diagonal tile) ----
        if (kt == qb) {
#pragma unroll
            for (int i = 0; i < 8; i++) {
                const int gq = ty * 8 + i;
#pragma unroll
                for (int j = 0; j < 8; j++) {
                    const int gk = tx * 8 + j;
                    s[i][j] = (gk <= gq) ? s[i][j] * ATT_SCALE : -1e30f;
                }
            }
        } else {
#pragma unroll
            for (int i = 0; i < 8; i++)
#pragma unroll
                for (int j = 0; j < 8; j++) s[i][j] *= ATT_SCALE;
        }

        // ---- online softmax (row groups = 16 threads sharing ty) ----
        float rmax[8];
#pragma unroll
        for (int i = 0; i < 8; i++) {
            float v01 = fmaxf(s[i][0], s[i][1]);
            float v23 = fmaxf(s[i][2], s[i][3]);
            float v45 = fmaxf(s[i][4], s[i][5]);
            float v67 = fmaxf(s[i][6], s[i][7]);
            rmax[i] = fmaxf(fmaxf(v01, v23), fmaxf(v45, v67));
        }
#pragma unroll
        for (int off = 1; off < 16; off <<= 1)
#pragma unroll
            for (int i = 0; i < 8; i++)
                rmax[i] = fmaxf(rmax[i], __shfl_xor_sync(0xffffffffu, rmax[i], off));

        float alpha[8];
#pragma unroll
        for (int i = 0; i < 8; i++) {
            const float mn = fmaxf(m[i], rmax[i]);
            alpha[i] = __expf(m[i] - mn);
            m[i] = mn;
        }

        float rsum[8];
#pragma unroll
        for (int i = 0; i < 8; i++) {
            rsum[i] = 0.f;
#pragma unroll
            for (int j = 0; j < 8; j++) {
                const float p = __expf(s[i][j] - m[i]);
                s[i][j] = p;
                rsum[i] += p;
            }
        }
#pragma unroll
        for (int off = 1; off < 16; off <<= 1)
#pragma unroll
            for (int i = 0; i < 8; i++)
                rsum[i] += __shfl_xor_sync(0xffffffffu, rsum[i], off);

#pragma unroll
        for (int i = 0; i < 8; i++) {
            l[i] = l[i] * alpha[i] + rsum[i];
#pragma unroll
            for (int c = 0; c < 4; c++) o[i][c] *= alpha[i];
        }

        // ---- store P row-major: Ps[q][k] ----
#pragma unroll
        for (int i = 0; i < 8; i++) {
            const int gq = ty * 8 + i;
            float4 p0 = make_float4(s[i][0], s[i][1], s[i][2], s[i][3]);
            float4 p1 = make_float4(s[i][4], s[i][5], s[i][6], s[i][7]);
            *(float4*)&Ps[gq * 128 + tx * 8]     = p0;
            *(float4*)&Ps[gq * 128 + tx * 8 + 4] = p1;
        }
        __syncthreads();

        // ---- O += P @ V ----
#pragma unroll 2
        for (int k4 = 0; k4 < 128; k4 += 4) {
            float4 pr[8], vr[4];
#pragma unroll
            for (int i = 0; i < 8; i++)
                pr[i] = *(float4*)&Ps[(ty * 8 + i) * 128 + k4];
#pragma unroll
            for (int kk = 0; kk < 4; kk++)
                vr[kk] = *(float4*)&Vs[(k4 + kk) * 64 + tx * 4];
#pragma unroll
            for (int i = 0; i < 8; i++) {
                o[i][0] += pr[i].x * vr[0].x + pr[i].y * vr[1].x +
                           pr[i].z * vr[2].x + pr[i].w * vr[3].x;
                o[i][1] += pr[i].x * vr[0].y + pr[i].y * vr[1].y +
                           pr[i].z * vr[2].y + pr[i].w * vr[3].y;
                o[i][2] += pr[i].x * vr[0].z + pr[i].y * vr[1].z +
                           pr[i].z * vr[2].z + pr[i].w * vr[3].z;
                o[i][3] += pr[i].x * vr[0].w + pr[i].y * vr[1].w +
                           pr[i].z * vr[2].w + pr[i].w * vr[3].w;
            }
        }
    }

    // ---- epilogue: normalize + store ----
#pragma unroll
    for (int i = 0; i < 8; i++) {
        const float inv = 1.f / l[i];
        const size_t row = (size_t)(q0 + ty * 8 + i);
        float4 r;
        r.x = o[i][0] * inv; r.y = o[i][1] * inv;
        r.z = o[i][2] * inv; r.w = o[i][3] * inv;
        *(float4*)&out[row * D_MODEL + h * HEAD_DIM + tx * 4] = r;
    }
}

// ---------------------------------------------------------------------------
extern "C" void kernel_launch(void* const* d_in, const int* in_sizes, int n_in,
                              void* d_out, int out_size)
{
    const float* x     = (const float*)d_in[0];
    const float* w_qkv = (const float*)d_in[1];
    const float* b_qkv = (const float*)d_in[2];
    const float* w_out = (const float*)d_in[3];
    const float* b_out = (const float*)d_in[4];
    float* out = (float*)d_out;

    float *qkv, *attn;
    cudaGetSymbolAddress((void**)&qkv, g_qkv);
    cudaGetSymbolAddress((void**)&attn, g_attn);

    const int flash_smem = (64 * 128 + 64 * 128 + 128 * 64 + 128 * 128) *
                           (int)sizeof(float);   // 163840 B
    cudaFuncSetAttribute(flash_attn_kernel,
                         cudaFuncAttributeMaxDynamicSharedMemorySize, flash_smem);

    // 1) qkv = x @ w_qkv + b_qkv
    {
        dim3 grid(QKV_COLS / 128, S_LEN / 128);
        gemm_bias_kernel<<<grid, 256>>>(x, w_qkv, b_qkv, qkv,
                                        S_LEN, QKV_COLS, D_MODEL);
    }

    // 2) causal flash attention -> attn
    {
        dim3 grid(S_LEN / 128, N_HEADS);
        flash_attn_kernel<<<grid, 256, flash_smem>>>(qkv, attn);
    }

    // 3) out = attn @ w_out + b_out
    {
        dim3 grid(D_MODEL / 128, S_LEN / 128);
        gemm_bias_kernel<<<grid, 256>>>(attn, w_out, b_out, out,
                                        S_LEN, D_MODEL, D_MODEL);
    }
}

// round 3
// speedup vs baseline: 1.5889x; 1.0432x over previous
#include <cuda_runtime.h>
#include <math.h>

#define S_LEN    4096
#define D_MODEL  1024
#define QKV_COLS 3072
#define N_HEADS  16
#define HEAD_DIM 64
#define ATT_SCALE 0.125f   // 1/sqrt(64)

typedef unsigned long long ull;

// packed f32x2 helpers (sm_100+): 2 fp32 MACs per issue slot
#define PACK2(d, x)   asm("mov.b64 %0, {%1, %1};" : "=l"(d) : "f"(x))
#define FMA2(d, a, b) asm("fma.rn.f32x2 %0, %1, %2, %0;" : "+l"(d) : "l"(a), "l"(b))
#define MUL2(d, a)    asm("mul.rn.f32x2 %0, %0, %1;" : "+l"(d) : "l"(a))
#define UNPACK2(lo, hi, s) asm("mov.b64 {%0, %1}, %2;" : "=f"(lo), "=f"(hi) : "l"(s))

union F4U { float4 f; ull u[2]; };

// Scratch (no cudaMalloc allowed)
static __device__ float g_qkv[S_LEN * QKV_COLS];    // [S, 3*D]
static __device__ float g_attn[S_LEN * D_MODEL];    // [S, D]

// ---------------------------------------------------------------------------
// SGEMM: C[M,N] = A[M,K] @ B[K,N] + bias[N]
// 128x128 block, BK=8, 256 threads, 8x8 per-thread tile, f32x2 FMAs.
// ---------------------------------------------------------------------------
__global__ __launch_bounds__(256)
void gemm_bias_kernel(const float* __restrict__ A, const float* __restrict__ B,
                      const float* __restrict__ bias, float* __restrict__ C,
                      int M, int N, int K)
{
    const int BM = 128, BN = 128, BK = 8;
    __shared__ float As[BK][BM];
    __shared__ float Bs[BK][BN];

    const int tid = threadIdx.x;
    const int bx = blockIdx.x, by = blockIdx.y;
    const int ty = tid >> 4;
    const int tx = tid & 15;

    const int rowA = tid >> 1;
    const int colA = (tid & 1) << 2;
    const int rowB = tid >> 5;
    const int colB = (tid & 31) << 2;

    const float* Ab = A + (size_t)(by * BM) * K;
    const float* Bb = B + (size_t)(bx * BN);

    ull acc2[8][4];
#pragma unroll
    for (int i = 0; i < 8; i++)
#pragma unroll
        for (int j = 0; j < 4; j++) acc2[i][j] = 0ull;

    for (int k0 = 0; k0 < K; k0 += BK) {
        float4 a4 = *(const float4*)(Ab + (size_t)rowA * K + k0 + colA);
        As[colA + 0][rowA] = a4.x;
        As[colA + 1][rowA] = a4.y;
        As[colA + 2][rowA] = a4.z;
        As[colA + 3][rowA] = a4.w;
        *(float4*)&Bs[rowB][colB] =
            *(const float4*)(Bb + (size_t)(k0 + rowB) * N + colB);
        __syncthreads();

#pragma unroll
        for (int kk = 0; kk < BK; kk++) {
            float rm[8];
            *(float4*)(rm)     = *(float4*)&As[kk][ty * 8];
            *(float4*)(rm + 4) = *(float4*)&As[kk][ty * 8 + 4];
            F4U b0, b1;
            b0.f = *(float4*)&Bs[kk][tx * 8];
            b1.f = *(float4*)&Bs[kk][tx * 8 + 4];
            ull rn2[4] = { b0.u[0], b0.u[1], b1.u[0], b1.u[1] };
#pragma unroll
            for (int i = 0; i < 8; i++) {
                ull am;
                PACK2(am, rm[i]);
#pragma unroll
                for (int j = 0; j < 4; j++)
                    FMA2(acc2[i][j], am, rn2[j]);
            }
        }
        __syncthreads();
    }

    const int colBase = bx * BN + tx * 8;
    float bv[8];
#pragma unroll
    for (int j = 0; j < 8; j++) bv[j] = bias[colBase + j];

#pragma unroll
    for (int i = 0; i < 8; i++) {
        const size_t row = (size_t)(by * BM + ty * 8 + i);
        float c[8];
#pragma unroll
        for (int j = 0; j < 4; j++)
            UNPACK2(c[2 * j], c[2 * j + 1], acc2[i][j]);
        float4 r0, r1;
        r0.x = c[0] + bv[0]; r0.y = c[1] + bv[1];
        r0.z = c[2] + bv[2]; r0.w = c[3] + bv[3];
        r1.x = c[4] + bv[4]; r1.y = c[5] + bv[5];
        r1.z = c[6] + bv[6]; r1.w = c[7] + bv[7];
        *(float4*)&C[row * N + colBase]     = r0;
        *(float4*)&C[row * N + colBase + 4] = r1;
    }
}

// ---------------------------------------------------------------------------
// Flash attention: 128x128 tiles, outer-product, f32x2 FMAs.
// smem: Qt 32K + Kt 32K + Vs 32K + Ps 64K = 160 KB (1 block/SM).
// ---------------------------------------------------------------------------
__global__ __launch_bounds__(256, 1)
void flash_attn_kernel(const float* __restrict__ qkv, float* __restrict__ out)
{
    extern __shared__ float sm[];
    float* Qt = sm;                   // [64][128]  Qt[d][q]
    float* Kt = Qt + 64 * 128;        // [64][128]  Kt[d][k]
    float* Vs = Kt + 64 * 128;        // [128][64]  Vs[k][c]
    float* Ps = Vs + 128 * 64;        // [128][128] Ps[q][k]

    const int qb  = blockIdx.x;
    const int h   = blockIdx.y;
    const int tid = threadIdx.x;
    const int ty  = tid >> 4;         // q rows ty*8..+7
    const int tx  = tid & 15;         // keys tx*8..+7 / out cols tx*4..+3
    const int q0  = qb * 128;

    // ---- load Q tile transposed ----
    {
        const float* Qg = qkv + (size_t)q0 * QKV_COLS + h * HEAD_DIM;
        const int r = tid >> 1;
        const int b = tid & 1;
#pragma unroll
        for (int p = 0; p < 8; p++) {
            const int c = (b + 2 * p) << 2;
            float4 v = *(const float4*)(Qg + (size_t)r * QKV_COLS + c);
            Qt[(c + 0) * 128 + r] = v.x;
            Qt[(c + 1) * 128 + r] = v.y;
            Qt[(c + 2) * 128 + r] = v.z;
            Qt[(c + 3) * 128 + r] = v.w;
        }
    }

    float m[8], l[8];
    ull o2[8][2];
#pragma unroll
    for (int i = 0; i < 8; i++) {
        m[i] = -1e30f; l[i] = 0.f;
        o2[i][0] = 0ull; o2[i][1] = 0ull;
    }

    for (int kt = 0; kt <= qb; kt++) {
        const int k0 = kt * 128;
        const float* Kg = qkv + (size_t)k0 * QKV_COLS + D_MODEL     + h * HEAD_DIM;
        const float* Vg = qkv + (size_t)k0 * QKV_COLS + 2 * D_MODEL + h * HEAD_DIM;

        __syncthreads();   // prev PV done (and Q visible on first iter)

        // ---- load K transposed ----
        {
            const int r = tid >> 1;
            const int b = tid & 1;
#pragma unroll
            for (int p = 0; p < 8; p++) {
                const int c = (b + 2 * p) << 2;
                float4 v = *(const float4*)(Kg + (size_t)r * QKV_COLS + c);
                Kt[(c + 0) * 128 + r] = v.x;
                Kt[(c + 1) * 128 + r] = v.y;
                Kt[(c + 2) * 128 + r] = v.z;
                Kt[(c + 3) * 128 + r] = v.w;
            }
        }
        // ---- load V row-major ----
#pragma unroll
        for (int i = 0; i < 8; i++) {
            const int idx = tid + i * 256;
            const int r = idx >> 4, c = (idx & 15) << 2;
            *(float4*)&Vs[r * 64 + c] =
                *(const float4*)(Vg + (size_t)r * QKV_COLS + c);
        }
        __syncthreads();

        // ---- scores: s = Q @ K^T, packed along k ----
        ull s2[8][4];
#pragma unroll
        for (int i = 0; i < 8; i++)
#pragma unroll
            for (int j = 0; j < 4; j++) s2[i][j] = 0ull;

#pragma unroll 4
        for (int d = 0; d < 64; d++) {
            float rm[8];
            *(float4*)(rm)     = *(float4*)&Qt[d * 128 + ty * 8];
            *(float4*)(rm + 4) = *(float4*)&Qt[d * 128 + ty * 8 + 4];
            F4U k0u, k1u;
            k0u.f = *(float4*)&Kt[d * 128 + tx * 8];
            k1u.f = *(float4*)&Kt[d * 128 + tx * 8 + 4];
            ull rn2[4] = { k0u.u[0], k0u.u[1], k1u.u[0], k1u.u[1] };
#pragma unroll
            for (int i = 0; i < 8; i++) {
                ull am;
                PACK2(am, rm[i]);
#pragma unroll
                for (int j = 0; j < 4; j++)
                    FMA2(s2[i][j], am, rn2[j]);
            }
        }

        // ---- unpack, scale + causal mask ----
        float s[8][8];
#pragma unroll
        for (int i = 0; i < 8; i++)
#pragma unroll
            for (int j = 0; j < 4; j++)
                UNPACK2(s[i][2 * j], s[i][2 * j + 1], s2[i][j]);

        if (kt == qb) {
#pragma unroll
            for (int i = 0; i < 8; i++) {
                const int gq = ty * 8 + i;
#pragma unroll
                for (int j = 0; j < 8; j++) {
                    const int gk = tx * 8 + j;
                    s[i][j] = (gk <= gq) ? s[i][j] * ATT_SCALE : -1e30f;
                }
            }
        } else {
#pragma unroll
            for (int i = 0; i < 8; i++)
#pragma unroll
                for (int j = 0; j < 8; j++) s[i][j] *= ATT_SCALE;
        }

        // ---- online softmax ----
        float rmax[8];
#pragma unroll
        for (int i = 0; i < 8; i++) {
            float v01 = fmaxf(s[i][0], s[i][1]);
            float v23 = fmaxf(s[i][2], s[i][3]);
            float v45 = fmaxf(s[i][4], s[i][5]);
            float v67 = fmaxf(s[i][6], s[i][7]);
            rmax[i] = fmaxf(fmaxf(v01, v23), fmaxf(v45, v67));
        }
#pragma unroll
        for (int off = 1; off < 16; off <<= 1)
#pragma unroll
            for (int i = 0; i < 8; i++)
                rmax[i] = fmaxf(rmax[i], __shfl_xor_sync(0xffffffffu, rmax[i], off));

        float alpha[8];
#pragma unroll
        for (int i = 0; i < 8; i++) {
            const float mn = fmaxf(m[i], rmax[i]);
            alpha[i] = __expf(m[i] - mn);
            m[i] = mn;
        }

        float rsum[8];
#pragma unroll
        for (int i = 0; i < 8; i++) {
            rsum[i] = 0.f;
#pragma unroll
            for (int j = 0; j < 8; j++) {
                const float p = __expf(s[i][j] - m[i]);
                s[i][j] = p;
                rsum[i] += p;
            }
        }
#pragma unroll
        for (int off = 1; off < 16; off <<= 1)
#pragma unroll
            for (int i = 0; i < 8; i++)
                rsum[i] += __shfl_xor_sync(0xffffffffu, rsum[i], off);

#pragma unroll
        for (int i = 0; i < 8; i++) {
            l[i] = l[i] * alpha[i] + rsum[i];
            ull av;
            PACK2(av, alpha[i]);
            MUL2(o2[i][0], av);
            MUL2(o2[i][1], av);
        }

        // ---- store P row-major ----
#pragma unroll
        for (int i = 0; i < 8; i++) {
            const int gq = ty * 8 + i;
            float4 p0 = make_float4(s[i][0], s[i][1], s[i][2], s[i][3]);
            float4 p1 = make_float4(s[i][4], s[i][5], s[i][6], s[i][7]);
            *(float4*)&Ps[gq * 128 + tx * 8]     = p0;
            *(float4*)&Ps[gq * 128 + tx * 8 + 4] = p1;
        }
        __syncthreads();

        // ---- O += P @ V  (packed along out-cols) ----
#pragma unroll 2
        for (int k4 = 0; k4 < 128; k4 += 4) {
            float4 pr[8];
            F4U vr[4];
#pragma unroll
            for (int i = 0; i < 8; i++)
                pr[i] = *(float4*)&Ps[(ty * 8 + i) * 128 + k4];
#pragma unroll
            for (int kk = 0; kk < 4; kk++)
                vr[kk].f = *(float4*)&Vs[(k4 + kk) * 64 + tx * 4];
#pragma unroll
            for (int i = 0; i < 8; i++) {
                ull pb;
                PACK2(pb, pr[i].x);
                FMA2(o2[i][0], pb, vr[0].u[0]);
                FMA2(o2[i][1], pb, vr[0].u[1]);
                PACK2(pb, pr[i].y);
                FMA2(o2[i][0], pb, vr[1].u[0]);
                FMA2(o2[i][1], pb, vr[1].u[1]);
                PACK2(pb, pr[i].z);
                FMA2(o2[i][0], pb, vr[2].u[0]);
                FMA2(o2[i][1], pb, vr[2].u[1]);
                PACK2(pb, pr[i].w);
                FMA2(o2[i][0], pb, vr[3].u[0]);
                FMA2(o2[i][1], pb, vr[3].u[1]);
            }
        }
    }

    // ---- epilogue ----
#pragma unroll
    for (int i = 0; i < 8; i++) {
        const float inv = 1.f / l[i];
        const size_t row = (size_t)(q0 + ty * 8 + i);
        float o[4];
        UNPACK2(o[0], o[1], o2[i][0]);
        UNPACK2(o[2], o[3], o2[i][1]);
        float4 r;
        r.x = o[0] * inv; r.y = o[1] * inv;
        r.z = o[2] * inv; r.w = o[3] * inv;
        *(float4*)&out[row * D_MODEL + h * HEAD_DIM + tx * 4] = r;
    }
}

// ---------------------------------------------------------------------------
extern "C" void kernel_launch(void* const* d_in, const int* in_sizes, int n_in,
                              void* d_out, int out_size)
{
    const float* x     = (const float*)d_in[0];
    const float* w_qkv = (const float*)d_in[1];
    const float* b_qkv = (const float*)d_in[2];
    const float* w_out = (const float*)d_in[3];
    const float* b_out = (const float*)d_in[4];
    float* out = (float*)d_out;

    float *qkv, *attn;
    cudaGetSymbolAddress((void**)&qkv, g_qkv);
    cudaGetSymbolAddress((void**)&attn, g_attn);

    const int flash_smem = (64 * 128 + 64 * 128 + 128 * 64 + 128 * 128) *
                           (int)sizeof(float);   // 163840 B
    cudaFuncSetAttribute(flash_attn_kernel,
                         cudaFuncAttributeMaxDynamicSharedMemorySize, flash_smem);

    // 1) qkv = x @ w_qkv + b_qkv
    {
        dim3 grid(QKV_COLS / 128, S_LEN / 128);
        gemm_bias_kernel<<<grid, 256>>>(x, w_qkv, b_qkv, qkv,
                                        S_LEN, QKV_COLS, D_MODEL);
    }

    // 2) causal flash attention -> attn
    {
        dim3 grid(S_LEN / 128, N_HEADS);
        flash_attn_kernel<<<grid, 256, flash_smem>>>(qkv, attn);
    }

    // 3) out = attn @ w_out + b_out
    {
        dim3 grid(D_MODEL / 128, S_LEN / 128);
        gemm_bias_kernel<<<grid, 256>>>(attn, w_out, b_out, out,
                                        S_LEN, D_MODEL, D_MODEL);
    }
}

// round 5
// speedup vs baseline: 1.9631x; 1.2355x over previous
#include <cuda_runtime.h>
#include <cuda_bf16.h>
#include <mma.h>
#include <cstdint>
#include <math.h>

using namespace nvcuda;

#define S_LEN    4096
#define D_MODEL  1024
#define QKV_COLS 3072
#define N_HEADS  16
#define HEAD_DIM 64
#define ATT_SCALE 0.125f

typedef unsigned long long ull;

// packed f32x2 helpers (attention kernel)
#define PACK2(d, x)   asm("mov.b64 %0, {%1, %1};" : "=l"(d) : "f"(x))
#define FMA2(d, a, b) asm("fma.rn.f32x2 %0, %1, %2, %0;" : "+l"(d) : "l"(a), "l"(b))
#define MUL2(d, a)    asm("mul.rn.f32x2 %0, %0, %1;" : "+l"(d) : "l"(a))
#define UNPACK2(lo, hi, s) asm("mov.b64 {%0, %1}, %2;" : "=f"(lo), "=f"(hi) : "l"(s))
union F4U { float4 f; ull u[2]; };

// ---------------- scratch (__device__ globals; no cudaMalloc) ----------------
static __device__ float g_qkv[S_LEN * QKV_COLS];
static __device__ float g_attn[S_LEN * D_MODEL];
static __device__ __align__(256) __nv_bfloat16 g_xh[S_LEN * D_MODEL];
static __device__ __align__(256) __nv_bfloat16 g_xl[S_LEN * D_MODEL];
static __device__ __align__(256) __nv_bfloat16 g_ah[S_LEN * D_MODEL];
static __device__ __align__(256) __nv_bfloat16 g_al[S_LEN * D_MODEL];
static __device__ __align__(256) __nv_bfloat16 g_wqh[QKV_COLS * D_MODEL]; // [N][K]
static __device__ __align__(256) __nv_bfloat16 g_wql[QKV_COLS * D_MODEL];
static __device__ __align__(256) __nv_bfloat16 g_woh[D_MODEL * D_MODEL];
static __device__ __align__(256) __nv_bfloat16 g_wol[D_MODEL * D_MODEL];

// ---------------- convert kernels ----------------
__global__ void split_rows_kernel(const float* __restrict__ src,
                                  __nv_bfloat16* __restrict__ hi,
                                  __nv_bfloat16* __restrict__ lo, int n)
{
    int i = (blockIdx.x * blockDim.x + threadIdx.x) * 4;
    if (i >= n) return;
    float4 v = *(const float4*)(src + i);
    __nv_bfloat16 h0 = __float2bfloat16(v.x), h1 = __float2bfloat16(v.y);
    __nv_bfloat16 h2 = __float2bfloat16(v.z), h3 = __float2bfloat16(v.w);
    __nv_bfloat16 l0 = __float2bfloat16(v.x - __bfloat162float(h0));
    __nv_bfloat16 l1 = __float2bfloat16(v.y - __bfloat162float(h1));
    __nv_bfloat16 l2 = __float2bfloat16(v.z - __bfloat162float(h2));
    __nv_bfloat16 l3 = __float2bfloat16(v.w - __bfloat162float(h3));
    hi[i] = h0; hi[i+1] = h1; hi[i+2] = h2; hi[i+3] = h3;
    lo[i] = l0; lo[i+1] = l1; lo[i+2] = l2; lo[i+3] = l3;
}

// transpose + split: w[K][N] fp32 -> wT hi/lo [N][K] bf16
__global__ void transpose_split_kernel(const float* __restrict__ w,
                                       __nv_bfloat16* __restrict__ hi,
                                       __nv_bfloat16* __restrict__ lo,
                                       int K, int N)
{
    __shared__ float tile[32][33];
    const int n0 = blockIdx.x * 32, k0 = blockIdx.y * 32;
    const int tx = threadIdx.x, ty = threadIdx.y;   // 32 x 8
#pragma unroll
    for (int i = 0; i < 4; i++)
        tile[ty + 8 * i][tx] = w[(size_t)(k0 + ty + 8 * i) * N + n0 + tx];
    __syncthreads();
#pragma unroll
    for (int i = 0; i < 4; i++) {
        const int r = ty + 8 * i;
        float v = tile[tx][r];
        __nv_bfloat16 h = __float2bfloat16(v);
        __nv_bfloat16 l = __float2bfloat16(v - __bfloat162float(h));
        hi[(size_t)(n0 + r) * K + k0 + tx] = h;
        lo[(size_t)(n0 + r) * K + k0 + tx] = l;
    }
}

// ---------------- wmma bf16 hi/lo GEMM: C[M,N] = (Ah+Al)(Bh+Bl)^T + bias ----
// A*: [M][K] bf16 K-major. B*: [N][K] bf16 K-major.
// 128x128 block tile, 256 threads (8 warps 2x4), warp tile 64x32, k-step 16.
#define GLD 24                               // smem row stride (bf16 elems)
#define GEMM_SMEM (128 * 132 * 4)            // epilogue fp32 staging dominates

__global__ __launch_bounds__(256)
void gemm_wmma_kernel(const __nv_bfloat16* __restrict__ Ah,
                      const __nv_bfloat16* __restrict__ Al,
                      const __nv_bfloat16* __restrict__ Bh,
                      const __nv_bfloat16* __restrict__ Bl,
                      const float* __restrict__ bias, float* __restrict__ C,
                      int M, int N, int K)
{
    extern __shared__ char smraw[];
    __nv_bfloat16* sAh = (__nv_bfloat16*)smraw;          // 128*GLD each
    __nv_bfloat16* sAl = sAh + 128 * GLD;
    __nv_bfloat16* sBh = sAl + 128 * GLD;
    __nv_bfloat16* sBl = sBh + 128 * GLD;
    float* Cs = (float*)smraw;                            // reused in epilogue

    const int tid = threadIdx.x;
    const int wid = tid >> 5;
    const int wr = wid >> 2;          // 0..1 -> rows wr*64
    const int wc = wid & 3;           // 0..3 -> cols wc*32
    const int m0 = blockIdx.y * 128, n0 = blockIdx.x * 128;

    wmma::fragment<wmma::accumulator, 16, 16, 16, float> acc[4][2];
#pragma unroll
    for (int i = 0; i < 4; i++)
#pragma unroll
        for (int j = 0; j < 2; j++) wmma::fill_fragment(acc[i][j], 0.0f);

    const int row = tid >> 1;         // 0..127
    const int half = tid & 1;         // 0/1 -> 8 bf16 each
    const __nv_bfloat16* pAh = Ah + (size_t)(m0 + row) * K + half * 8;
    const __nv_bfloat16* pAl = Al + (size_t)(m0 + row) * K + half * 8;
    const __nv_bfloat16* pBh = Bh + (size_t)(n0 + row) * K + half * 8;
    const __nv_bfloat16* pBl = Bl + (size_t)(n0 + row) * K + half * 8;
    const int soff = row * GLD + half * 8;

    for (int k0 = 0; k0 < K; k0 += 16) {
        *(uint4*)&sAh[soff] = *(const uint4*)(pAh + k0);
        *(uint4*)&sAl[soff] = *(const uint4*)(pAl + k0);
        *(uint4*)&sBh[soff] = *(const uint4*)(pBh + k0);
        *(uint4*)&sBl[soff] = *(const uint4*)(pBl + k0);
        __syncthreads();

        wmma::fragment<wmma::matrix_a, 16, 16, 16, __nv_bfloat16, wmma::row_major> ah[4], al[4];
        wmma::fragment<wmma::matrix_b, 16, 16, 16, __nv_bfloat16, wmma::col_major> bh[2], bl[2];
#pragma unroll
        for (int i = 0; i < 4; i++) {
            wmma::load_matrix_sync(ah[i], &sAh[(wr * 64 + i * 16) * GLD], GLD);
            wmma::load_matrix_sync(al[i], &sAl[(wr * 64 + i * 16) * GLD], GLD);
        }
#pragma unroll
        for (int j = 0; j < 2; j++) {
            wmma::load_matrix_sync(bh[j], &sBh[(wc * 32 + j * 16) * GLD], GLD);
            wmma::load_matrix_sync(bl[j], &sBl[(wc * 32 + j * 16) * GLD], GLD);
        }
#pragma unroll
        for (int i = 0; i < 4; i++)
#pragma unroll
            for (int j = 0; j < 2; j++) {
                wmma::mma_sync(acc[i][j], ah[i], bh[j], acc[i][j]);
                wmma::mma_sync(acc[i][j], ah[i], bl[j], acc[i][j]);
                wmma::mma_sync(acc[i][j], al[i], bh[j], acc[i][j]);
            }
        __syncthreads();
    }

    // epilogue: frags -> smem -> (bias add) -> coalesced global stores
#pragma unroll
    for (int i = 0; i < 4; i++)
#pragma unroll
        for (int j = 0; j < 2; j++)
            wmma::store_matrix_sync(&Cs[(wr * 64 + i * 16) * 132 + wc * 32 + j * 16],
                                    acc[i][j], 132, wmma::mem_row_major);
    __syncthreads();

    {
        const int r = tid >> 1;
        const int cb = (tid & 1) * 64;
        float* cp = C + (size_t)(m0 + r) * N + n0 + cb;
        const float* bp = bias + n0 + cb;
        const float* sp = &Cs[r * 132 + cb];
#pragma unroll
        for (int j = 0; j < 64; j += 4) {
            float4 o;
            o.x = sp[j + 0] + bp[j + 0];
            o.y = sp[j + 1] + bp[j + 1];
            o.z = sp[j + 2] + bp[j + 2];
            o.w = sp[j + 3] + bp[j + 3];
            *(float4*)(cp + j) = o;
        }
    }
}

// ---------------------------------------------------------------------------
// Flash attention (R3 version, f32x2): 128x128 tiles, outer product.
// ---------------------------------------------------------------------------
__global__ __launch_bounds__(256, 1)
void flash_attn_kernel(const float* __restrict__ qkv, float* __restrict__ out)
{
    extern __shared__ float sm[];
    float* Qt = sm;
    float* Kt = Qt + 64 * 128;
    float* Vs = Kt + 64 * 128;
    float* Ps = Vs + 128 * 64;

    const int qb  = blockIdx.x;
    const int h   = blockIdx.y;
    const int tid = threadIdx.x;
    const int ty  = tid >> 4;
    const int tx  = tid & 15;
    const int q0  = qb * 128;

    {
        const float* Qg = qkv + (size_t)q0 * QKV_COLS + h * HEAD_DIM;
        const int r = tid >> 1;
        const int b = tid & 1;
#pragma unroll
        for (int p = 0; p < 8; p++) {
            const int c = (b + 2 * p) << 2;
            float4 v = *(const float4*)(Qg + (size_t)r * QKV_COLS + c);
            Qt[(c + 0) * 128 + r] = v.x;
            Qt[(c + 1) * 128 + r] = v.y;
            Qt[(c + 2) * 128 + r] = v.z;
            Qt[(c + 3) * 128 + r] = v.w;
        }
    }

    float m[8], l[8];
    ull o2[8][2];
#pragma unroll
    for (int i = 0; i < 8; i++) {
        m[i] = -1e30f; l[i] = 0.f;
        o2[i][0] = 0ull; o2[i][1] = 0ull;
    }

    for (int kt = 0; kt <= qb; kt++) {
        const int k0 = kt * 128;
        const float* Kg = qkv + (size_t)k0 * QKV_COLS + D_MODEL     + h * HEAD_DIM;
        const float* Vg = qkv + (size_t)k0 * QKV_COLS + 2 * D_MODEL + h * HEAD_DIM;

        __syncthreads();

        {
            const int r = tid >> 1;
            const int b = tid & 1;
#pragma unroll
            for (int p = 0; p < 8; p++) {
                const int c = (b + 2 * p) << 2;
                float4 v = *(const float4*)(Kg + (size_t)r * QKV_COLS + c);
                Kt[(c + 0) * 128 + r] = v.x;
                Kt[(c + 1) * 128 + r] = v.y;
                Kt[(c + 2) * 128 + r] = v.z;
                Kt[(c + 3) * 128 + r] = v.w;
            }
        }
#pragma unroll
        for (int i = 0; i < 8; i++) {
            const int idx = tid + i * 256;
            const int r = idx >> 4, c = (idx & 15) << 2;
            *(float4*)&Vs[r * 64 + c] =
                *(const float4*)(Vg + (size_t)r * QKV_COLS + c);
        }
        __syncthreads();

        ull s2[8][4];
#pragma unroll
        for (int i = 0; i < 8; i++)
#pragma unroll
            for (int j = 0; j < 4; j++) s2[i][j] = 0ull;

#pragma unroll 4
        for (int d = 0; d < 64; d++) {
            float rm[8];
            *(float4*)(rm)     = *(float4*)&Qt[d * 128 + ty * 8];
            *(float4*)(rm + 4) = *(float4*)&Qt[d * 128 + ty * 8 + 4];
            F4U k0u, k1u;
            k0u.f = *(float4*)&Kt[d * 128 + tx * 8];
            k1u.f = *(float4*)&Kt[d * 128 + tx * 8 + 4];
            ull rn2[4] = { k0u.u[0], k0u.u[1], k1u.u[0], k1u.u[1] };
#pragma unroll
            for (int i = 0; i < 8; i++) {
                ull am;
                PACK2(am, rm[i]);
#pragma unroll
                for (int j = 0; j < 4; j++)
                    FMA2(s2[i][j], am, rn2[j]);
            }
        }

        float s[8][8];
#pragma unroll
        for (int i = 0; i < 8; i++)
#pragma unroll
            for (int j = 0; j < 4; j++)
                UNPACK2(s[i][2 * j], s[i][2 * j + 1], s2[i][j]);

        if (kt == qb) {
#pragma unroll
            for (int i = 0; i < 8; i++) {
                const int gq = ty * 8 + i;
#pragma unroll
                for (int j = 0; j < 8; j++) {
                    const int gk = tx * 8 + j;
                    s[i][j] = (gk <= gq) ? s[i][j] * ATT_SCALE : -1e30f;
                }
            }
        } else {
#pragma unroll
            for (int i = 0; i < 8; i++)
#pragma unroll
                for (int j = 0; j < 8; j++) s[i][j] *= ATT_SCALE;
        }

        float rmax[8];
#pragma unroll
        for (int i = 0; i < 8; i++) {
            float v01 = fmaxf(s[i][0], s[i][1]);
            float v23 = fmaxf(s[i][2], s[i][3]);
            float v45 = fmaxf(s[i][4], s[i][5]);
            float v67 = fmaxf(s[i][6], s[i][7]);
            rmax[i] = fmaxf(fmaxf(v01, v23), fmaxf(v45, v67));
        }
#pragma unroll
        for (int off = 1; off < 16; off <<= 1)
#pragma unroll
            for (int i = 0; i < 8; i++)
                rmax[i] = fmaxf(rmax[i], __shfl_xor_sync(0xffffffffu, rmax[i], off));

        float alpha[8];
#pragma unroll
        for (int i = 0; i < 8; i++) {
            const float mn = fmaxf(m[i], rmax[i]);
            alpha[i] = __expf(m[i] - mn);
            m[i] = mn;
        }

        float rsum[8];
#pragma unroll
        for (int i = 0; i < 8; i++) {
            rsum[i] = 0.f;
#pragma unroll
            for (int j = 0; j < 8; j++) {
                const float p = __expf(s[i][j] - m[i]);
                s[i][j] = p;
                rsum[i] += p;
            }
        }
#pragma unroll
        for (int off = 1; off < 16; off <<= 1)
#pragma unroll
            for (int i = 0; i < 8; i++)
                rsum[i] += __shfl_xor_sync(0xffffffffu, rsum[i], off);

#pragma unroll
        for (int i = 0; i < 8; i++) {
            l[i] = l[i] * alpha[i] + rsum[i];
            ull av;
            PACK2(av, alpha[i]);
            MUL2(o2[i][0], av);
            MUL2(o2[i][1], av);
        }

#pragma unroll
        for (int i = 0; i < 8; i++) {
            const int gq = ty * 8 + i;
            float4 p0 = make_float4(s[i][0], s[i][1], s[i][2], s[i][3]);
            float4 p1 = make_float4(s[i][4], s[i][5], s[i][6], s[i][7]);
            *(float4*)&Ps[gq * 128 + tx * 8]     = p0;
            *(float4*)&Ps[gq * 128 + tx * 8 + 4] = p1;
        }
        __syncthreads();

#pragma unroll 2
        for (int k4 = 0; k4 < 128; k4 += 4) {
            float4 pr[8];
            F4U vr[4];
#pragma unroll
            for (int i = 0; i < 8; i++)
                pr[i] = *(float4*)&Ps[(ty * 8 + i) * 128 + k4];
#pragma unroll
            for (int kk = 0; kk < 4; kk++)
                vr[kk].f = *(float4*)&Vs[(k4 + kk) * 64 + tx * 4];
#pragma unroll
            for (int i = 0; i < 8; i++) {
                ull pb;
                PACK2(pb, pr[i].x);
                FMA2(o2[i][0], pb, vr[0].u[0]);
                FMA2(o2[i][1], pb, vr[0].u[1]);
                PACK2(pb, pr[i].y);
                FMA2(o2[i][0], pb, vr[1].u[0]);
                FMA2(o2[i][1], pb, vr[1].u[1]);
                PACK2(pb, pr[i].z);
                FMA2(o2[i][0], pb, vr[2].u[0]);
                FMA2(o2[i][1], pb, vr[2].u[1]);
                PACK2(pb, pr[i].w);
                FMA2(o2[i][0], pb, vr[3].u[0]);
                FMA2(o2[i][1], pb, vr[3].u[1]);
            }
        }
    }

#pragma unroll
    for (int i = 0; i < 8; i++) {
        const float inv = 1.f / l[i];
        const size_t row = (size_t)(q0 + ty * 8 + i);
        float o[4];
        UNPACK2(o[0], o[1], o2[i][0]);
        UNPACK2(o[2], o[3], o2[i][1]);
        float4 r;
        r.x = o[0] * inv; r.y = o[1] * inv;
        r.z = o[2] * inv; r.w = o[3] * inv;
        *(float4*)&out[row * D_MODEL + h * HEAD_DIM + tx * 4] = r;
    }
}

// ---------------------------------------------------------------------------
extern "C" void kernel_launch(void* const* d_in, const int* in_sizes, int n_in,
                              void* d_out, int out_size)
{
    const float* x     = (const float*)d_in[0];
    const float* w_qkv = (const float*)d_in[1];
    const float* b_qkv = (const float*)d_in[2];
    const float* w_out = (const float*)d_in[3];
    const float* b_out = (const float*)d_in[4];
    float* out = (float*)d_out;

    float *qkv, *attn;
    cudaGetSymbolAddress((void**)&qkv, g_qkv);
    cudaGetSymbolAddress((void**)&attn, g_attn);
    __nv_bfloat16 *xh, *xl, *ah, *al, *wqh, *wql, *woh, *wol;
    cudaGetSymbolAddress((void**)&xh, g_xh);
    cudaGetSymbolAddress((void**)&xl, g_xl);
    cudaGetSymbolAddress((void**)&ah, g_ah);
    cudaGetSymbolAddress((void**)&al, g_al);
    cudaGetSymbolAddress((void**)&wqh, g_wqh);
    cudaGetSymbolAddress((void**)&wql, g_wql);
    cudaGetSymbolAddress((void**)&woh, g_woh);
    cudaGetSymbolAddress((void**)&wol, g_wol);

    const int flash_smem = (64 * 128 + 64 * 128 + 128 * 64 + 128 * 128) *
                           (int)sizeof(float);
    cudaFuncSetAttribute(flash_attn_kernel,
                         cudaFuncAttributeMaxDynamicSharedMemorySize, flash_smem);
    cudaFuncSetAttribute(gemm_wmma_kernel,
                         cudaFuncAttributeMaxDynamicSharedMemorySize, GEMM_SMEM);

    // prep: x -> bf16 hi/lo; weights -> transposed bf16 hi/lo
    {
        const int nx = S_LEN * D_MODEL;
        split_rows_kernel<<<nx / (256 * 4), 256>>>(x, xh, xl, nx);
        dim3 g1(QKV_COLS / 32, D_MODEL / 32), b1(32, 8);
        transpose_split_kernel<<<g1, b1>>>(w_qkv, wqh, wql, D_MODEL, QKV_COLS);
        dim3 g2(D_MODEL / 32, D_MODEL / 32);
        transpose_split_kernel<<<g2, b1>>>(w_out, woh, wol, D_MODEL, D_MODEL);
    }

    // 1) qkv = x @ w_qkv + b_qkv   (wmma bf16 hi/lo)
    {
        dim3 grid(QKV_COLS / 128, S_LEN / 128);
        gemm_wmma_kernel<<<grid, 256, GEMM_SMEM>>>(xh, xl, wqh, wql, b_qkv, qkv,
                                                   S_LEN, QKV_COLS, D_MODEL);
    }

    // 2) causal flash attention -> attn
    {
        dim3 grid(S_LEN / 128, N_HEADS);
        flash_attn_kernel<<<grid, 256, flash_smem>>>(qkv, attn);
    }

    // 3) attn -> bf16 hi/lo; out = attn @ w_out + b_out (wmma)
    {
        const int na = S_LEN * D_MODEL;
        split_rows_kernel<<<na / (256 * 4), 256>>>(attn, ah, al, na);
        dim3 grid(D_MODEL / 128, S_LEN / 128);
        gemm_wmma_kernel<<<grid, 256, GEMM_SMEM>>>(ah, al, woh, wol, b_out, out,
                                                   S_LEN, D_MODEL, D_MODEL);
    }
}

// round 7
// speedup vs baseline: 3.2652x; 1.6632x over previous
#include <cuda_runtime.h>
#include <cuda_bf16.h>
#include <mma.h>
#include <cstdint>
#include <math.h>

using namespace nvcuda;

#define S_LEN    4096
#define D_MODEL  1024
#define QKV_COLS 3072
#define N_HEADS  16
#define HEAD_DIM 64
#define ATT_SCALE 0.125f

// ---------------- scratch (__device__ globals; no cudaMalloc) ----------------
static __device__ __align__(256) __nv_bfloat16 g_xh[S_LEN * D_MODEL];
static __device__ __align__(256) __nv_bfloat16 g_xl[S_LEN * D_MODEL];
static __device__ __align__(256) __nv_bfloat16 g_qh[S_LEN * QKV_COLS];
static __device__ __align__(256) __nv_bfloat16 g_ql[S_LEN * QKV_COLS];
static __device__ __align__(256) __nv_bfloat16 g_ah[S_LEN * D_MODEL];
static __device__ __align__(256) __nv_bfloat16 g_al[S_LEN * D_MODEL];
static __device__ __align__(256) __nv_bfloat16 g_wqh[QKV_COLS * D_MODEL]; // [N][K]
static __device__ __align__(256) __nv_bfloat16 g_wql[QKV_COLS * D_MODEL];
static __device__ __align__(256) __nv_bfloat16 g_woh[D_MODEL * D_MODEL];
static __device__ __align__(256) __nv_bfloat16 g_wol[D_MODEL * D_MODEL];

// ---------------- PTX helpers ----------------
__device__ __forceinline__ uint32_t smem_u32(const void* p) {
    uint32_t a;
    asm("{ .reg .u64 t; cvta.to.shared.u64 t, %1; cvt.u32.u64 %0, t; }"
        : "=r"(a) : "l"(p));
    return a;
}
__device__ __forceinline__ void ldsm_x4(uint32_t* r, uint32_t addr) {
    asm volatile("ldmatrix.sync.aligned.m8n8.x4.shared.b16 {%0,%1,%2,%3}, [%4];"
                 : "=r"(r[0]), "=r"(r[1]), "=r"(r[2]), "=r"(r[3]) : "r"(addr));
}
__device__ __forceinline__ void ldsm_x4_t(uint32_t* r, uint32_t addr) {
    asm volatile("ldmatrix.sync.aligned.m8n8.x4.trans.shared.b16 {%0,%1,%2,%3}, [%4];"
                 : "=r"(r[0]), "=r"(r[1]), "=r"(r[2]), "=r"(r[3]) : "r"(addr));
}
__device__ __forceinline__ void mma_bf16(float* c, const uint32_t* a, const uint32_t* b) {
    asm volatile("mma.sync.aligned.m16n8k16.row.col.f32.bf16.bf16.f32 "
                 "{%0,%1,%2,%3}, {%4,%5,%6,%7}, {%8,%9}, {%0,%1,%2,%3};"
                 : "+f"(c[0]), "+f"(c[1]), "+f"(c[2]), "+f"(c[3])
                 : "r"(a[0]), "r"(a[1]), "r"(a[2]), "r"(a[3]), "r"(b[0]), "r"(b[1]));
}
// split two fp32 into packed bf16x2 hi + bf16x2 lo
__device__ __forceinline__ void split_pack(float x, float y, uint32_t& hi, uint32_t& lo) {
    __nv_bfloat16 hx = __float2bfloat16(x), hy = __float2bfloat16(y);
    __nv_bfloat16 lx = __float2bfloat16(x - __bfloat162float(hx));
    __nv_bfloat16 ly = __float2bfloat16(y - __bfloat162float(hy));
    hi = ((uint32_t)__bfloat16_as_ushort(hy) << 16) | __bfloat16_as_ushort(hx);
    lo = ((uint32_t)__bfloat16_as_ushort(ly) << 16) | __bfloat16_as_ushort(lx);
}

// ---------------- convert kernels ----------------
__global__ void split_rows_kernel(const float* __restrict__ src,
                                  __nv_bfloat16* __restrict__ hi,
                                  __nv_bfloat16* __restrict__ lo, int n)
{
    int i = (blockIdx.x * blockDim.x + threadIdx.x) * 4;
    if (i >= n) return;
    float4 v = *(const float4*)(src + i);
    __nv_bfloat16 h0 = __float2bfloat16(v.x), h1 = __float2bfloat16(v.y);
    __nv_bfloat16 h2 = __float2bfloat16(v.z), h3 = __float2bfloat16(v.w);
    hi[i] = h0; hi[i+1] = h1; hi[i+2] = h2; hi[i+3] = h3;
    lo[i]   = __float2bfloat16(v.x - __bfloat162float(h0));
    lo[i+1] = __float2bfloat16(v.y - __bfloat162float(h1));
    lo[i+2] = __float2bfloat16(v.z - __bfloat162float(h2));
    lo[i+3] = __float2bfloat16(v.w - __bfloat162float(h3));
}

__global__ void transpose_split_kernel(const float* __restrict__ w,
                                       __nv_bfloat16* __restrict__ hi,
                                       __nv_bfloat16* __restrict__ lo,
                                       int K, int N)
{
    __shared__ float tile[32][33];
    const int n0 = blockIdx.x * 32, k0 = blockIdx.y * 32;
    const int tx = threadIdx.x, ty = threadIdx.y;   // 32 x 8
#pragma unroll
    for (int i = 0; i < 4; i++)
        tile[ty + 8 * i][tx] = w[(size_t)(k0 + ty + 8 * i) * N + n0 + tx];
    __syncthreads();
#pragma unroll
    for (int i = 0; i < 4; i++) {
        const int r = ty + 8 * i;
        float v = tile[tx][r];
        __nv_bfloat16 h = __float2bfloat16(v);
        hi[(size_t)(n0 + r) * K + k0 + tx] = h;
        lo[(size_t)(n0 + r) * K + k0 + tx] =
            __float2bfloat16(v - __bfloat162float(h));
    }
}

// ---------------- wmma bf16 hi/lo GEMM ----------------
#define GLD 24
#define GEMM_SMEM (128 * 132 * 4)

__global__ __launch_bounds__(256)
void gemm_wmma_kernel(const __nv_bfloat16* __restrict__ Ah,
                      const __nv_bfloat16* __restrict__ Al,
                      const __nv_bfloat16* __restrict__ Bh,
                      const __nv_bfloat16* __restrict__ Bl,
                      const float* __restrict__ bias,
                      float* __restrict__ Cf,
                      __nv_bfloat16* __restrict__ Ch,
                      __nv_bfloat16* __restrict__ Cl,
                      int hilo, int M, int N, int K)
{
    extern __shared__ char smraw[];
    __nv_bfloat16* sAh = (__nv_bfloat16*)smraw;
    __nv_bfloat16* sAl = sAh + 128 * GLD;
    __nv_bfloat16* sBh = sAl + 128 * GLD;
    __nv_bfloat16* sBl = sBh + 128 * GLD;
    float* Cs = (float*)smraw;

    const int tid = threadIdx.x;
    const int wid = tid >> 5;
    const int wr = wid >> 2;
    const int wc = wid & 3;
    const int m0 = blockIdx.y * 128, n0 = blockIdx.x * 128;

    wmma::fragment<wmma::accumulator, 16, 16, 16, float> acc[4][2];
#pragma unroll
    for (int i = 0; i < 4; i++)
#pragma unroll
        for (int j = 0; j < 2; j++) wmma::fill_fragment(acc[i][j], 0.0f);

    const int row = tid >> 1;
    const int half = tid & 1;
    const __nv_bfloat16* pAh = Ah + (size_t)(m0 + row) * K + half * 8;
    const __nv_bfloat16* pAl = Al + (size_t)(m0 + row) * K + half * 8;
    const __nv_bfloat16* pBh = Bh + (size_t)(n0 + row) * K + half * 8;
    const __nv_bfloat16* pBl = Bl + (size_t)(n0 + row) * K + half * 8;
    const int soff = row * GLD + half * 8;

    for (int k0 = 0; k0 < K; k0 += 16) {
        *(uint4*)&sAh[soff] = *(const uint4*)(pAh + k0);
        *(uint4*)&sAl[soff] = *(const uint4*)(pAl + k0);
        *(uint4*)&sBh[soff] = *(const uint4*)(pBh + k0);
        *(uint4*)&sBl[soff] = *(const uint4*)(pBl + k0);
        __syncthreads();

        wmma::fragment<wmma::matrix_a, 16, 16, 16, __nv_bfloat16, wmma::row_major> ah[4], al[4];
        wmma::fragment<wmma::matrix_b, 16, 16, 16, __nv_bfloat16, wmma::col_major> bh[2], bl[2];
#pragma unroll
        for (int i = 0; i < 4; i++) {
            wmma::load_matrix_sync(ah[i], &sAh[(wr * 64 + i * 16) * GLD], GLD);
            wmma::load_matrix_sync(al[i], &sAl[(wr * 64 + i * 16) * GLD], GLD);
        }
#pragma unroll
        for (int j = 0; j < 2; j++) {
            wmma::load_matrix_sync(bh[j], &sBh[(wc * 32 + j * 16) * GLD], GLD);
            wmma::load_matrix_sync(bl[j], &sBl[(wc * 32 + j * 16) * GLD], GLD);
        }
#pragma unroll
        for (int i = 0; i < 4; i++)
#pragma unroll
            for (int j = 0; j < 2; j++) {
                wmma::mma_sync(acc[i][j], ah[i], bh[j], acc[i][j]);
                wmma::mma_sync(acc[i][j], ah[i], bl[j], acc[i][j]);
                wmma::mma_sync(acc[i][j], al[i], bh[j], acc[i][j]);
            }
        __syncthreads();
    }

#pragma unroll
    for (int i = 0; i < 4; i++)
#pragma unroll
        for (int j = 0; j < 2; j++)
            wmma::store_matrix_sync(&Cs[(wr * 64 + i * 16) * 132 + wc * 32 + j * 16],
                                    acc[i][j], 132, wmma::mem_row_major);
    __syncthreads();

    {
        const int r = tid >> 1;
        const int cb = (tid & 1) * 64;
        const float* bp = bias + n0 + cb;
        const float* sp = &Cs[r * 132 + cb];
        if (!hilo) {
            float* cp = Cf + (size_t)(m0 + r) * N + n0 + cb;
#pragma unroll
            for (int j = 0; j < 64; j += 4) {
                float4 o;
                o.x = sp[j+0] + bp[j+0]; o.y = sp[j+1] + bp[j+1];
                o.z = sp[j+2] + bp[j+2]; o.w = sp[j+3] + bp[j+3];
                *(float4*)(cp + j) = o;
            }
        } else {
            __nv_bfloat16* hp = Ch + (size_t)(m0 + r) * N + n0 + cb;
            __nv_bfloat16* lp = Cl + (size_t)(m0 + r) * N + n0 + cb;
#pragma unroll
            for (int j = 0; j < 64; j += 4) {
                uint32_t h0, l0, h1, l1;
                split_pack(sp[j+0] + bp[j+0], sp[j+1] + bp[j+1], h0, l0);
                split_pack(sp[j+2] + bp[j+2], sp[j+3] + bp[j+3], h1, l1);
                *(uint2*)(hp + j) = make_uint2(h0, h1);
                *(uint2*)(lp + j) = make_uint2(l0, l1);
            }
        }
    }
}

// ---------------------------------------------------------------------------
// Flash attention on mma.sync bf16 (hi/lo split), FA2 register-resident style.
// Grid (32, 16), block 256 = 8 warps; warp owns 16 q-rows x full 128-key tile.
// ---------------------------------------------------------------------------
#define ALD 72           // smem row stride in bf16 elems (64 + 8 pad)
#define FA_SMEM (6 * 128 * ALD * 2)   // Qh Ql Kh Kl Vh Vl = 110592 B

__global__ __launch_bounds__(256, 1)
void flash_attn_mma_kernel(const __nv_bfloat16* __restrict__ qh,
                           const __nv_bfloat16* __restrict__ ql,
                           __nv_bfloat16* __restrict__ oh,
                           __nv_bfloat16* __restrict__ ol)
{
    extern __shared__ char smraw[];
    __nv_bfloat16* sQh = (__nv_bfloat16*)smraw;
    __nv_bfloat16* sQl = sQh + 128 * ALD;
    __nv_bfloat16* sKh = sQl + 128 * ALD;
    __nv_bfloat16* sKl = sKh + 128 * ALD;
    __nv_bfloat16* sVh = sKl + 128 * ALD;
    __nv_bfloat16* sVl = sVh + 128 * ALD;

    const int qb  = gridDim.x - 1 - blockIdx.x;   // long rows first
    const int h   = blockIdx.y;
    const int tid = threadIdx.x;
    const int wid = tid >> 5;
    const int lane = tid & 31;
    const int q0  = qb * 128;

    const int g  = lane >> 2;                       // quad row 0..7
    const int t  = lane & 3;                        // quad col
    const int lr = lane & 15;                       // ldsm row pattern (A/V)
    const int lc8 = (lane >> 4) * 8;                // ldsm col half (A/V)
    const int kk = (lane & 7) + ((lane & 16) >> 1); // ldsm key row (K)
    const int kd8 = lane & 8;                       // ldsm d half (K)

    const uint32_t uQh = smem_u32(sQh), uQl = smem_u32(sQl);
    const uint32_t uKh = smem_u32(sKh), uKl = smem_u32(sKl);
    const uint32_t uVh = smem_u32(sVh), uVl = smem_u32(sVl);

    // ---- load Q tile (hi/lo) ----
    {
        const int colQ = h * HEAD_DIM;
#pragma unroll
        for (int i = 0; i < 4; i++) {
            const int idx = tid + i * 256;        // 0..1023
            const int r = idx >> 3, c = (idx & 7) * 8;
            const size_t gofs = (size_t)(q0 + r) * QKV_COLS + colQ + c;
            *(uint4*)(sQh + r * ALD + c) = *(const uint4*)(qh + gofs);
            *(uint4*)(sQl + r * ALD + c) = *(const uint4*)(ql + gofs);
        }
    }

    float ofr[8][4];
    float m0 = -1e30f, m1 = -1e30f, l0 = 0.f, l1 = 0.f;
#pragma unroll
    for (int j = 0; j < 8; j++)
#pragma unroll
        for (int e = 0; e < 4; e++) ofr[j][e] = 0.f;

    const int colK = D_MODEL + h * HEAD_DIM;
    const int colV = 2 * D_MODEL + h * HEAD_DIM;

    for (int kt = 0; kt <= qb; kt++) {
        const int k0 = kt * 128;
        __syncthreads();   // previous tile fully consumed (Q visible on iter 0)

        // ---- load K/V tiles (hi/lo) ----
#pragma unroll
        for (int i = 0; i < 4; i++) {
            const int idx = tid + i * 256;
            const int r = idx >> 3, c = (idx & 7) * 8;
            const size_t gr = (size_t)(k0 + r) * QKV_COLS;
            *(uint4*)(sKh + r * ALD + c) = *(const uint4*)(qh + gr + colK + c);
            *(uint4*)(sKl + r * ALD + c) = *(const uint4*)(ql + gr + colK + c);
            *(uint4*)(sVh + r * ALD + c) = *(const uint4*)(qh + gr + colV + c);
            *(uint4*)(sVl + r * ALD + c) = *(const uint4*)(ql + gr + colV + c);
        }
        __syncthreads();

        // ---- S = (Qh+Ql)(Kh+Kl)^T : 16 C-frags (key n8-blocks) ----
        float sfr[16][4];
#pragma unroll
        for (int j = 0; j < 16; j++)
#pragma unroll
            for (int e = 0; e < 4; e++) sfr[j][e] = 0.f;

#pragma unroll
        for (int u = 0; u < 4; u++) {              // d-step 16u
            uint32_t aQh[4], aQl[4];
            const uint32_t qoff =
                (uint32_t)(((wid * 16 + lr) * ALD + 16 * u + lc8) * 2);
            ldsm_x4(aQh, uQh + qoff);
            ldsm_x4(aQl, uQl + qoff);
#pragma unroll
            for (int jj = 0; jj < 8; jj++) {       // key 16-block
                uint32_t bKh[4], bKl[4];
                const uint32_t koff =
                    (uint32_t)(((16 * jj + kk) * ALD + 16 * u + kd8) * 2);
                ldsm_x4(bKh, uKh + koff);
                ldsm_x4(bKl, uKl + koff);
                mma_bf16(sfr[2*jj],   aQh, bKh);
                mma_bf16(sfr[2*jj+1], aQh, bKh + 2);
                mma_bf16(sfr[2*jj],   aQh, bKl);
                mma_bf16(sfr[2*jj+1], aQh, bKl + 2);
                mma_bf16(sfr[2*jj],   aQl, bKh);
                mma_bf16(sfr[2*jj+1], aQl, bKh + 2);
            }
        }

        // ---- scale + causal mask (local coords; diagonal tile only) ----
        if (kt == qb) {
            const int gq0 = wid * 16 + g, gq1 = gq0 + 8;
#pragma unroll
            for (int j = 0; j < 16; j++) {
                const int c = 8 * j + 2 * t;
                sfr[j][0] = (c     <= gq0) ? sfr[j][0] * ATT_SCALE : -1e30f;
                sfr[j][1] = (c + 1 <= gq0) ? sfr[j][1] * ATT_SCALE : -1e30f;
                sfr[j][2] = (c     <= gq1) ? sfr[j][2] * ATT_SCALE : -1e30f;
                sfr[j][3] = (c + 1 <= gq1) ? sfr[j][3] * ATT_SCALE : -1e30f;
            }
        } else {
#pragma unroll
            for (int j = 0; j < 16; j++) {
                sfr[j][0] *= ATT_SCALE; sfr[j][1] *= ATT_SCALE;
                sfr[j][2] *= ATT_SCALE; sfr[j][3] *= ATT_SCALE;
            }
        }

        // ---- online softmax (rows g / g+8; reduce across quad lanes) ----
        float mn0 = m0, mn1 = m1;
#pragma unroll
        for (int j = 0; j < 16; j++) {
            mn0 = fmaxf(mn0, fmaxf(sfr[j][0], sfr[j][1]));
            mn1 = fmaxf(mn1, fmaxf(sfr[j][2], sfr[j][3]));
        }
        mn0 = fmaxf(mn0, __shfl_xor_sync(0xffffffffu, mn0, 1));
        mn0 = fmaxf(mn0, __shfl_xor_sync(0xffffffffu, mn0, 2));
        mn1 = fmaxf(mn1, __shfl_xor_sync(0xffffffffu, mn1, 1));
        mn1 = fmaxf(mn1, __shfl_xor_sync(0xffffffffu, mn1, 2));

        const float alpha0 = __expf(m0 - mn0);
        const float alpha1 = __expf(m1 - mn1);
        m0 = mn0; m1 = mn1;

        float sum0 = 0.f, sum1 = 0.f;
#pragma unroll
        for (int j = 0; j < 16; j++) {
            sfr[j][0] = __expf(sfr[j][0] - mn0);
            sfr[j][1] = __expf(sfr[j][1] - mn0);
            sfr[j][2] = __expf(sfr[j][2] - mn1);
            sfr[j][3] = __expf(sfr[j][3] - mn1);
            sum0 += sfr[j][0] + sfr[j][1];
            sum1 += sfr[j][2] + sfr[j][3];
        }
        sum0 += __shfl_xor_sync(0xffffffffu, sum0, 1);
        sum0 += __shfl_xor_sync(0xffffffffu, sum0, 2);
        sum1 += __shfl_xor_sync(0xffffffffu, sum1, 1);
        sum1 += __shfl_xor_sync(0xffffffffu, sum1, 2);
        l0 = l0 * alpha0 + sum0;
        l1 = l1 * alpha1 + sum1;

#pragma unroll
        for (int j = 0; j < 8; j++) {
            ofr[j][0] *= alpha0; ofr[j][1] *= alpha0;
            ofr[j][2] *= alpha1; ofr[j][3] *= alpha1;
        }

        // ---- O += P @ V  (P -> hi/lo A-frags built per key-block u) ----
#pragma unroll
        for (int u = 0; u < 8; u++) {              // key step 16u
            uint32_t aPh[4], aPl[4];
            split_pack(sfr[2*u][0],   sfr[2*u][1],   aPh[0], aPl[0]);
            split_pack(sfr[2*u][2],   sfr[2*u][3],   aPh[1], aPl[1]);
            split_pack(sfr[2*u+1][0], sfr[2*u+1][1], aPh[2], aPl[2]);
            split_pack(sfr[2*u+1][2], sfr[2*u+1][3], aPh[3], aPl[3]);
#pragma unroll
            for (int cc = 0; cc < 4; cc++) {       // out-col 16-block
                uint32_t bVh[4], bVl[4];
                const uint32_t voff =
                    (uint32_t)(((16 * u + lr) * ALD + 16 * cc + lc8) * 2);
                ldsm_x4_t(bVh, uVh + voff);
                ldsm_x4_t(bVl, uVl + voff);
                // regs (0,1) = B-frag for n-cols 16cc..+7; (2,3) = +8..+15
                mma_bf16(ofr[2*cc],     aPh, bVh);
                mma_bf16(ofr[2*cc],     aPl, bVh);
                mma_bf16(ofr[2*cc],     aPh, bVl);
                mma_bf16(ofr[2*cc + 1], aPh, bVh + 2);
                mma_bf16(ofr[2*cc + 1], aPl, bVh + 2);
                mma_bf16(ofr[2*cc + 1], aPh, bVl + 2);
            }
        }
    }

    // ---- epilogue: normalize, split hi/lo, store ----
    const float inv0 = 1.f / l0, inv1 = 1.f / l1;
    const int row0 = q0 + wid * 16 + g, row1 = row0 + 8;
#pragma unroll
    for (int j = 0; j < 8; j++) {
        const int c = h * HEAD_DIM + 8 * j + 2 * t;
        uint32_t hv, lv;
        split_pack(ofr[j][0] * inv0, ofr[j][1] * inv0, hv, lv);
        *(uint32_t*)(oh + (size_t)row0 * D_MODEL + c) = hv;
        *(uint32_t*)(ol + (size_t)row0 * D_MODEL + c) = lv;
        split_pack(ofr[j][2] * inv1, ofr[j][3] * inv1, hv, lv);
        *(uint32_t*)(oh + (size_t)row1 * D_MODEL + c) = hv;
        *(uint32_t*)(ol + (size_t)row1 * D_MODEL + c) = lv;
    }
}

// ---------------------------------------------------------------------------
extern "C" void kernel_launch(void* const* d_in, const int* in_sizes, int n_in,
                              void* d_out, int out_size)
{
    const float* x     = (const float*)d_in[0];
    const float* w_qkv = (const float*)d_in[1];
    const float* b_qkv = (const float*)d_in[2];
    const float* w_out = (const float*)d_in[3];
    const float* b_out = (const float*)d_in[4];
    float* out = (float*)d_out;

    __nv_bfloat16 *xh, *xl, *qh, *ql, *ah, *al, *wqh, *wql, *woh, *wol;
    cudaGetSymbolAddress((void**)&xh, g_xh);
    cudaGetSymbolAddress((void**)&xl, g_xl);
    cudaGetSymbolAddress((void**)&qh, g_qh);
    cudaGetSymbolAddress((void**)&ql, g_ql);
    cudaGetSymbolAddress((void**)&ah, g_ah);
    cudaGetSymbolAddress((void**)&al, g_al);
    cudaGetSymbolAddress((void**)&wqh, g_wqh);
    cudaGetSymbolAddress((void**)&wql, g_wql);
    cudaGetSymbolAddress((void**)&woh, g_woh);
    cudaGetSymbolAddress((void**)&wol, g_wol);

    cudaFuncSetAttribute(gemm_wmma_kernel,
                         cudaFuncAttributeMaxDynamicSharedMemorySize, GEMM_SMEM);
    cudaFuncSetAttribute(flash_attn_mma_kernel,
                         cudaFuncAttributeMaxDynamicSharedMemorySize, FA_SMEM);

    {
        const int nx = S_LEN * D_MODEL;
        split_rows_kernel<<<nx / (256 * 4), 256>>>(x, xh, xl, nx);
        dim3 g1(QKV_COLS / 32, D_MODEL / 32), b1(32, 8);
        transpose_split_kernel<<<g1, b1>>>(w_qkv, wqh, wql, D_MODEL, QKV_COLS);
        dim3 g2(D_MODEL / 32, D_MODEL / 32);
        transpose_split_kernel<<<g2, b1>>>(w_out, woh, wol, D_MODEL, D_MODEL);
    }

    // 1) qkv (bf16 hi/lo) = x @ w_qkv + b_qkv
    {
        dim3 grid(QKV_COLS / 128, S_LEN / 128);
        gemm_wmma_kernel<<<grid, 256, GEMM_SMEM>>>(xh, xl, wqh, wql, b_qkv,
                                                   nullptr, qh, ql, 1,
                                                   S_LEN, QKV_COLS, D_MODEL);
    }
    // 2) attention -> ah/al (bf16 hi/lo)
    {
        dim3 grid(S_LEN / 128, N_HEADS);
        flash_attn_mma_kernel<<<grid, 256, FA_SMEM>>>(qh, ql, ah, al);
    }
    // 3) out = attn @ w_out + b_out (fp32)
    {
        dim3 grid(D_MODEL / 128, S_LEN / 128);
        gemm_wmma_kernel<<<grid, 256, GEMM_SMEM>>>(ah, al, woh, wol, b_out,
                                                   out, nullptr, nullptr, 0,
                                                   S_LEN, D_MODEL, D_MODEL);
    }
}

// round 8
// speedup vs baseline: 3.6648x; 1.1224x over previous
#include <cuda_runtime.h>
#include <cuda_bf16.h>
#include <mma.h>
#include <cstdint>
#include <math.h>

using namespace nvcuda;

#define S_LEN    4096
#define D_MODEL  1024
#define QKV_COLS 3072
#define N_HEADS  16
#define HEAD_DIM 64
#define ATT_SCALE 0.125f

// ---------------- scratch (__device__ globals; no cudaMalloc) ----------------
static __device__ __align__(256) __nv_bfloat16 g_xh[S_LEN * D_MODEL];
static __device__ __align__(256) __nv_bfloat16 g_xl[S_LEN * D_MODEL];
static __device__ __align__(256) __nv_bfloat16 g_qh[S_LEN * QKV_COLS];
static __device__ __align__(256) __nv_bfloat16 g_ql[S_LEN * QKV_COLS];
static __device__ __align__(256) __nv_bfloat16 g_ah[S_LEN * D_MODEL];
static __device__ __align__(256) __nv_bfloat16 g_al[S_LEN * D_MODEL];
static __device__ __align__(256) __nv_bfloat16 g_wqh[QKV_COLS * D_MODEL]; // [N][K]
static __device__ __align__(256) __nv_bfloat16 g_wql[QKV_COLS * D_MODEL];
static __device__ __align__(256) __nv_bfloat16 g_woh[D_MODEL * D_MODEL];
static __device__ __align__(256) __nv_bfloat16 g_wol[D_MODEL * D_MODEL];

// ---------------- PTX helpers ----------------
__device__ __forceinline__ uint32_t smem_u32(const void* p) {
    uint32_t a;
    asm("{ .reg .u64 t; cvta.to.shared.u64 t, %1; cvt.u32.u64 %0, t; }"
        : "=r"(a) : "l"(p));
    return a;
}
__device__ __forceinline__ void cp_async16(uint32_t saddr, const void* gptr) {
    asm volatile("cp.async.cg.shared.global [%0], [%1], 16;"
                 :: "r"(saddr), "l"(gptr));
}
#define CP_COMMIT() asm volatile("cp.async.commit_group;" ::: "memory")
#define CP_WAIT(n)  asm volatile("cp.async.wait_group %0;" :: "n"(n) : "memory")

__device__ __forceinline__ void ldsm_x4(uint32_t* r, uint32_t addr) {
    asm volatile("ldmatrix.sync.aligned.m8n8.x4.shared.b16 {%0,%1,%2,%3}, [%4];"
                 : "=r"(r[0]), "=r"(r[1]), "=r"(r[2]), "=r"(r[3]) : "r"(addr));
}
__device__ __forceinline__ void ldsm_x4_t(uint32_t* r, uint32_t addr) {
    asm volatile("ldmatrix.sync.aligned.m8n8.x4.trans.shared.b16 {%0,%1,%2,%3}, [%4];"
                 : "=r"(r[0]), "=r"(r[1]), "=r"(r[2]), "=r"(r[3]) : "r"(addr));
}
__device__ __forceinline__ void mma_bf16(float* c, const uint32_t* a, const uint32_t* b) {
    asm volatile("mma.sync.aligned.m16n8k16.row.col.f32.bf16.bf16.f32 "
                 "{%0,%1,%2,%3}, {%4,%5,%6,%7}, {%8,%9}, {%0,%1,%2,%3};"
                 : "+f"(c[0]), "+f"(c[1]), "+f"(c[2]), "+f"(c[3])
                 : "r"(a[0]), "r"(a[1]), "r"(a[2]), "r"(a[3]), "r"(b[0]), "r"(b[1]));
}
__device__ __forceinline__ void split_pack(float x, float y, uint32_t& hi, uint32_t& lo) {
    __nv_bfloat16 hx = __float2bfloat16(x), hy = __float2bfloat16(y);
    __nv_bfloat16 lx = __float2bfloat16(x - __bfloat162float(hx));
    __nv_bfloat16 ly = __float2bfloat16(y - __bfloat162float(hy));
    hi = ((uint32_t)__bfloat16_as_ushort(hy) << 16) | __bfloat16_as_ushort(hx);
    lo = ((uint32_t)__bfloat16_as_ushort(ly) << 16) | __bfloat16_as_ushort(lx);
}

// ---------------- convert kernels ----------------
__global__ void split_rows_kernel(const float* __restrict__ src,
                                  __nv_bfloat16* __restrict__ hi,
                                  __nv_bfloat16* __restrict__ lo, int n)
{
    int i = (blockIdx.x * blockDim.x + threadIdx.x) * 4;
    if (i >= n) return;
    float4 v = *(const float4*)(src + i);
    __nv_bfloat16 h0 = __float2bfloat16(v.x), h1 = __float2bfloat16(v.y);
    __nv_bfloat16 h2 = __float2bfloat16(v.z), h3 = __float2bfloat16(v.w);
    hi[i] = h0; hi[i+1] = h1; hi[i+2] = h2; hi[i+3] = h3;
    lo[i]   = __float2bfloat16(v.x - __bfloat162float(h0));
    lo[i+1] = __float2bfloat16(v.y - __bfloat162float(h1));
    lo[i+2] = __float2bfloat16(v.z - __bfloat162float(h2));
    lo[i+3] = __float2bfloat16(v.w - __bfloat162float(h3));
}

__global__ void transpose_split_kernel(const float* __restrict__ w,
                                       __nv_bfloat16* __restrict__ hi,
                                       __nv_bfloat16* __restrict__ lo,
                                       int K, int N)
{
    __shared__ float tile[32][33];
    const int n0 = blockIdx.x * 32, k0 = blockIdx.y * 32;
    const int tx = threadIdx.x, ty = threadIdx.y;   // 32 x 8
#pragma unroll
    for (int i = 0; i < 4; i++)
        tile[ty + 8 * i][tx] = w[(size_t)(k0 + ty + 8 * i) * N + n0 + tx];
    __syncthreads();
#pragma unroll
    for (int i = 0; i < 4; i++) {
        const int r = ty + 8 * i;
        float v = tile[tx][r];
        __nv_bfloat16 h = __float2bfloat16(v);
        hi[(size_t)(n0 + r) * K + k0 + tx] = h;
        lo[(size_t)(n0 + r) * K + k0 + tx] =
            __float2bfloat16(v - __bfloat162float(h));
    }
}

// ---------------- wmma bf16 hi/lo GEMM, cp.async double-buffered ----------------
#define GLD 24
#define GTILE  (128 * GLD * 2)          // 6144 B per tile
#define GSTAGE (4 * GTILE)              // 24576 B per stage
#define GEMM_SMEM (128 * 132 * 4)       // 67584 B (epilogue dominates; stages alias)

__global__ __launch_bounds__(256)
void gemm_wmma_kernel(const __nv_bfloat16* __restrict__ Ah,
                      const __nv_bfloat16* __restrict__ Al,
                      const __nv_bfloat16* __restrict__ Bh,
                      const __nv_bfloat16* __restrict__ Bl,
                      const float* __restrict__ bias,
                      float* __restrict__ Cf,
                      __nv_bfloat16* __restrict__ Ch,
                      __nv_bfloat16* __restrict__ Cl,
                      int hilo, int M, int N, int K)
{
    extern __shared__ char smraw[];
    float* Cs = (float*)smraw;
    const uint32_t sb = smem_u32(smraw);

    const int tid = threadIdx.x;
    const int wid = tid >> 5;
    const int wr = wid >> 2;
    const int wc = wid & 3;
    const int m0 = blockIdx.y * 128, n0 = blockIdx.x * 128;

    wmma::fragment<wmma::accumulator, 16, 16, 16, float> acc[4][2];
#pragma unroll
    for (int i = 0; i < 4; i++)
#pragma unroll
        for (int j = 0; j < 2; j++) wmma::fill_fragment(acc[i][j], 0.0f);

    const int row = tid >> 1;
    const int half = tid & 1;
    const __nv_bfloat16* pAh = Ah + (size_t)(m0 + row) * K + half * 8;
    const __nv_bfloat16* pAl = Al + (size_t)(m0 + row) * K + half * 8;
    const __nv_bfloat16* pBh = Bh + (size_t)(n0 + row) * K + half * 8;
    const __nv_bfloat16* pBl = Bl + (size_t)(n0 + row) * K + half * 8;
    const uint32_t soff = (uint32_t)(row * GLD + half * 8) * 2;  // bytes

    const int NT = K / 16;

    // prefetch stage 0
    {
        const uint32_t st = sb;
        cp_async16(st + soff,             pAh);
        cp_async16(st + GTILE + soff,     pAl);
        cp_async16(st + 2 * GTILE + soff, pBh);
        cp_async16(st + 3 * GTILE + soff, pBl);
        CP_COMMIT();
    }

    for (int kt = 0; kt < NT; kt++) {
        __syncthreads();   // next-stage buffer free (readers of kt-1 done)
        if (kt + 1 < NT) {
            const int k1 = (kt + 1) * 16;
            const uint32_t st = sb + ((kt + 1) & 1) * GSTAGE;
            cp_async16(st + soff,             pAh + k1);
            cp_async16(st + GTILE + soff,     pAl + k1);
            cp_async16(st + 2 * GTILE + soff, pBh + k1);
            cp_async16(st + 3 * GTILE + soff, pBl + k1);
            CP_COMMIT();
            CP_WAIT(1);
        } else {
            CP_WAIT(0);
        }
        __syncthreads();   // stage kt visible to all

        const __nv_bfloat16* stg =
            (const __nv_bfloat16*)(smraw + (kt & 1) * GSTAGE);
        const __nv_bfloat16* sAh = stg;
        const __nv_bfloat16* sAl = stg + 128 * GLD;
        const __nv_bfloat16* sBh = stg + 2 * 128 * GLD;
        const __nv_bfloat16* sBl = stg + 3 * 128 * GLD;

        wmma::fragment<wmma::matrix_a, 16, 16, 16, __nv_bfloat16, wmma::row_major> ah[4], al[4];
        wmma::fragment<wmma::matrix_b, 16, 16, 16, __nv_bfloat16, wmma::col_major> bh[2], bl[2];
#pragma unroll
        for (int i = 0; i < 4; i++) {
            wmma::load_matrix_sync(ah[i], &sAh[(wr * 64 + i * 16) * GLD], GLD);
            wmma::load_matrix_sync(al[i], &sAl[(wr * 64 + i * 16) * GLD], GLD);
        }
#pragma unroll
        for (int j = 0; j < 2; j++) {
            wmma::load_matrix_sync(bh[j], &sBh[(wc * 32 + j * 16) * GLD], GLD);
            wmma::load_matrix_sync(bl[j], &sBl[(wc * 32 + j * 16) * GLD], GLD);
        }
#pragma unroll
        for (int i = 0; i < 4; i++)
#pragma unroll
            for (int j = 0; j < 2; j++) {
                wmma::mma_sync(acc[i][j], ah[i], bh[j], acc[i][j]);
                wmma::mma_sync(acc[i][j], ah[i], bl[j], acc[i][j]);
                wmma::mma_sync(acc[i][j], al[i], bh[j], acc[i][j]);
            }
    }

    __syncthreads();   // all ldsm done before Cs overwrites stage smem
#pragma unroll
    for (int i = 0; i < 4; i++)
#pragma unroll
        for (int j = 0; j < 2; j++)
            wmma::store_matrix_sync(&Cs[(wr * 64 + i * 16) * 132 + wc * 32 + j * 16],
                                    acc[i][j], 132, wmma::mem_row_major);
    __syncthreads();

    {
        const int r = tid >> 1;
        const int cb = (tid & 1) * 64;
        const float* bp = bias + n0 + cb;
        const float* sp = &Cs[r * 132 + cb];
        if (!hilo) {
            float* cp = Cf + (size_t)(m0 + r) * N + n0 + cb;
#pragma unroll
            for (int j = 0; j < 64; j += 4) {
                float4 o;
                o.x = sp[j+0] + bp[j+0]; o.y = sp[j+1] + bp[j+1];
                o.z = sp[j+2] + bp[j+2]; o.w = sp[j+3] + bp[j+3];
                *(float4*)(cp + j) = o;
            }
        } else {
            __nv_bfloat16* hp = Ch + (size_t)(m0 + r) * N + n0 + cb;
            __nv_bfloat16* lp = Cl + (size_t)(m0 + r) * N + n0 + cb;
#pragma unroll
            for (int j = 0; j < 64; j += 4) {
                uint32_t h0, l0, h1, l1;
                split_pack(sp[j+0] + bp[j+0], sp[j+1] + bp[j+1], h0, l0);
                split_pack(sp[j+2] + bp[j+2], sp[j+3] + bp[j+3], h1, l1);
                *(uint2*)(hp + j) = make_uint2(h0, h1);
                *(uint2*)(lp + j) = make_uint2(l0, l1);
            }
        }
    }
}

// ---------------------------------------------------------------------------
// Flash attention on mma.sync bf16 (hi/lo), cp.async double-buffered K/V.
// Grid (32, 16), block 256 = 8 warps; warp owns 16 q-rows x 128-key tile.
// ---------------------------------------------------------------------------
#define ALD 72                              // bf16 elems per smem row
#define FARR (128 * ALD * 2)                // 18432 B per array
#define FA_KVSTAGE (4 * FARR)               // Kh Kl Vh Vl = 73728 B
#define FA_KVBASE  (2 * FARR)               // after Qh Ql
#define FA_SMEM (FA_KVBASE + 2 * FA_KVSTAGE)  // 184320 B

__global__ __launch_bounds__(256, 1)
void flash_attn_mma_kernel(const __nv_bfloat16* __restrict__ qh,
                           const __nv_bfloat16* __restrict__ ql,
                           __nv_bfloat16* __restrict__ oh,
                           __nv_bfloat16* __restrict__ ol)
{
    extern __shared__ char smraw[];
    __nv_bfloat16* sQh = (__nv_bfloat16*)smraw;
    __nv_bfloat16* sQl = sQh + 128 * ALD;
    const uint32_t sb = smem_u32(smraw);

    const int qb  = gridDim.x - 1 - blockIdx.x;   // long rows first
    const int h   = blockIdx.y;
    const int tid = threadIdx.x;
    const int wid = tid >> 5;
    const int lane = tid & 31;
    const int q0  = qb * 128;

    const int g  = lane >> 2;
    const int t  = lane & 3;
    const int lr = lane & 15;
    const int lc8 = (lane >> 4) * 8;
    const int kk = (lane & 7) + ((lane & 16) >> 1);
    const int kd8 = lane & 8;

    const int colK = D_MODEL + h * HEAD_DIM;
    const int colV = 2 * D_MODEL + h * HEAD_DIM;

    // per-thread cp.async chunk coords (4 chunks per array)
    int crow[4], cbyte[4];
#pragma unroll
    for (int i = 0; i < 4; i++) {
        const int idx = tid + i * 256;            // 0..1023
        crow[i]  = idx >> 3;
        cbyte[i] = (idx & 7) * 16;                // byte offset within row data
    }

    // ---- load Q tile (plain) ----
#pragma unroll
    for (int i = 0; i < 4; i++) {
        const int r = crow[i], c = cbyte[i] / 2;  // elems
        const size_t gofs = (size_t)(q0 + r) * QKV_COLS + h * HEAD_DIM + c;
        *(uint4*)(sQh + r * ALD + c) = *(const uint4*)(qh + gofs);
        *(uint4*)(sQl + r * ALD + c) = *(const uint4*)(ql + gofs);
    }

    // ---- prefetch K/V stage 0 ----
    {
        const uint32_t st = sb + FA_KVBASE;
#pragma unroll
        for (int i = 0; i < 4; i++) {
            const int r = crow[i];
            const uint32_t so = (uint32_t)(r * ALD * 2 + cbyte[i]);
            const size_t gr = (size_t)r * QKV_COLS;   // k0 = 0
            const int c = cbyte[i] / 2;
            cp_async16(st + so,            qh + gr + colK + c);
            cp_async16(st + FARR + so,     ql + gr + colK + c);
            cp_async16(st + 2 * FARR + so, qh + gr + colV + c);
            cp_async16(st + 3 * FARR + so, ql + gr + colV + c);
        }
        CP_COMMIT();
    }

    float ofr[8][4];
    float m0 = -1e30f, m1 = -1e30f, l0 = 0.f, l1 = 0.f;
#pragma unroll
    for (int j = 0; j < 8; j++)
#pragma unroll
        for (int e = 0; e < 4; e++) ofr[j][e] = 0.f;

    for (int kt = 0; kt <= qb; kt++) {
        __syncthreads();   // next-stage buffer free
        if (kt + 1 <= qb) {
            const int k1 = (kt + 1) * 128;
            const uint32_t st = sb + FA_KVBASE + ((kt + 1) & 1) * FA_KVSTAGE;
#pragma unroll
            for (int i = 0; i < 4; i++) {
                const int r = crow[i];
                const uint32_t so = (uint32_t)(r * ALD * 2 + cbyte[i]);
                const size_t gr = (size_t)(k1 + r) * QKV_COLS;
                const int c = cbyte[i] / 2;
                cp_async16(st + so,            qh + gr + colK + c);
                cp_async16(st + FARR + so,     ql + gr + colK + c);
                cp_async16(st + 2 * FARR + so, qh + gr + colV + c);
                cp_async16(st + 3 * FARR + so, ql + gr + colV + c);
            }
            CP_COMMIT();
            CP_WAIT(1);
        } else {
            CP_WAIT(0);
        }
        __syncthreads();   // stage kt visible

        const uint32_t stg = sb + FA_KVBASE + (kt & 1) * FA_KVSTAGE;
        const uint32_t uKh = stg, uKl = stg + FARR;
        const uint32_t uVh = stg + 2 * FARR, uVl = stg + 3 * FARR;
        const uint32_t uQh = sb, uQl = sb + FARR;

        // ---- S = (Qh+Ql)(Kh+Kl)^T ----
        float sfr[16][4];
#pragma unroll
        for (int j = 0; j < 16; j++)
#pragma unroll
            for (int e = 0; e < 4; e++) sfr[j][e] = 0.f;

#pragma unroll
        for (int u = 0; u < 4; u++) {
            uint32_t aQh[4], aQl[4];
            const uint32_t qoff =
                (uint32_t)(((wid * 16 + lr) * ALD + 16 * u + lc8) * 2);
            ldsm_x4(aQh, uQh + qoff);
            ldsm_x4(aQl, uQl + qoff);
#pragma unroll
            for (int jj = 0; jj < 8; jj++) {
                uint32_t bKh[4], bKl[4];
                const uint32_t koff =
                    (uint32_t)(((16 * jj + kk) * ALD + 16 * u + kd8) * 2);
                ldsm_x4(bKh, uKh + koff);
                ldsm_x4(bKl, uKl + koff);
                mma_bf16(sfr[2*jj],   aQh, bKh);
                mma_bf16(sfr[2*jj+1], aQh, bKh + 2);
                mma_bf16(sfr[2*jj],   aQh, bKl);
                mma_bf16(sfr[2*jj+1], aQh, bKl + 2);
                mma_bf16(sfr[2*jj],   aQl, bKh);
                mma_bf16(sfr[2*jj+1], aQl, bKh + 2);
            }
        }

        // ---- scale + causal mask ----
        if (kt == qb) {
            const int gq0 = wid * 16 + g, gq1 = gq0 + 8;
#pragma unroll
            for (int j = 0; j < 16; j++) {
                const int c = 8 * j + 2 * t;
                sfr[j][0] = (c     <= gq0) ? sfr[j][0] * ATT_SCALE : -1e30f;
                sfr[j][1] = (c + 1 <= gq0) ? sfr[j][1] * ATT_SCALE : -1e30f;
                sfr[j][2] = (c     <= gq1) ? sfr[j][2] * ATT_SCALE : -1e30f;
                sfr[j][3] = (c + 1 <= gq1) ? sfr[j][3] * ATT_SCALE : -1e30f;
            }
        } else {
#pragma unroll
            for (int j = 0; j < 16; j++) {
                sfr[j][0] *= ATT_SCALE; sfr[j][1] *= ATT_SCALE;
                sfr[j][2] *= ATT_SCALE; sfr[j][3] *= ATT_SCALE;
            }
        }

        // ---- online softmax ----
        float mn0 = m0, mn1 = m1;
#pragma unroll
        for (int j = 0; j < 16; j++) {
            mn0 = fmaxf(mn0, fmaxf(sfr[j][0], sfr[j][1]));
            mn1 = fmaxf(mn1, fmaxf(sfr[j][2], sfr[j][3]));
        }
        mn0 = fmaxf(mn0, __shfl_xor_sync(0xffffffffu, mn0, 1));
        mn0 = fmaxf(mn0, __shfl_xor_sync(0xffffffffu, mn0, 2));
        mn1 = fmaxf(mn1, __shfl_xor_sync(0xffffffffu, mn1, 1));
        mn1 = fmaxf(mn1, __shfl_xor_sync(0xffffffffu, mn1, 2));

        const float alpha0 = __expf(m0 - mn0);
        const float alpha1 = __expf(m1 - mn1);
        m0 = mn0; m1 = mn1;

        float sum0 = 0.f, sum1 = 0.f;
#pragma unroll
        for (int j = 0; j < 16; j++) {
            sfr[j][0] = __expf(sfr[j][0] - mn0);
            sfr[j][1] = __expf(sfr[j][1] - mn0);
            sfr[j][2] = __expf(sfr[j][2] - mn1);
            sfr[j][3] = __expf(sfr[j][3] - mn1);
            sum0 += sfr[j][0] + sfr[j][1];
            sum1 += sfr[j][2] + sfr[j][3];
        }
        sum0 += __shfl_xor_sync(0xffffffffu, sum0, 1);
        sum0 += __shfl_xor_sync(0xffffffffu, sum0, 2);
        sum1 += __shfl_xor_sync(0xffffffffu, sum1, 1);
        sum1 += __shfl_xor_sync(0xffffffffu, sum1, 2);
        l0 = l0 * alpha0 + sum0;
        l1 = l1 * alpha1 + sum1;

#pragma unroll
        for (int j = 0; j < 8; j++) {
            ofr[j][0] *= alpha0; ofr[j][1] *= alpha0;
            ofr[j][2] *= alpha1; ofr[j][3] *= alpha1;
        }

        // ---- O += P @ V ----
#pragma unroll
        for (int u = 0; u < 8; u++) {
            uint32_t aPh[4], aPl[4];
            split_pack(sfr[2*u][0],   sfr[2*u][1],   aPh[0], aPl[0]);
            split_pack(sfr[2*u][2],   sfr[2*u][3],   aPh[1], aPl[1]);
            split_pack(sfr[2*u+1][0], sfr[2*u+1][1], aPh[2], aPl[2]);
            split_pack(sfr[2*u+1][2], sfr[2*u+1][3], aPh[3], aPl[3]);
#pragma unroll
            for (int cc = 0; cc < 4; cc++) {
                uint32_t bVh[4], bVl[4];
                const uint32_t voff =
                    (uint32_t)(((16 * u + lr) * ALD + 16 * cc + lc8) * 2);
                ldsm_x4_t(bVh, uVh + voff);
                ldsm_x4_t(bVl, uVl + voff);
                mma_bf16(ofr[2*cc],     aPh, bVh);
                mma_bf16(ofr[2*cc],     aPl, bVh);
                mma_bf16(ofr[2*cc],     aPh, bVl);
                mma_bf16(ofr[2*cc + 1], aPh, bVh + 2);
                mma_bf16(ofr[2*cc + 1], aPl, bVh + 2);
                mma_bf16(ofr[2*cc + 1], aPh, bVl + 2);
            }
        }
    }

    // ---- epilogue ----
    const float inv0 = 1.f / l0, inv1 = 1.f / l1;
    const int row0 = q0 + wid * 16 + g, row1 = row0 + 8;
#pragma unroll
    for (int j = 0; j < 8; j++) {
        const int c = h * HEAD_DIM + 8 * j + 2 * t;
        uint32_t hv, lv;
        split_pack(ofr[j][0] * inv0, ofr[j][1] * inv0, hv, lv);
        *(uint32_t*)(oh + (size_t)row0 * D_MODEL + c) = hv;
        *(uint32_t*)(ol + (size_t)row0 * D_MODEL + c) = lv;
        split_pack(ofr[j][2] * inv1, ofr[j][3] * inv1, hv, lv);
        *(uint32_t*)(oh + (size_t)row1 * D_MODEL + c) = hv;
        *(uint32_t*)(ol + (size_t)row1 * D_MODEL + c) = lv;
    }
}

// ---------------------------------------------------------------------------
extern "C" void kernel_launch(void* const* d_in, const int* in_sizes, int n_in,
                              void* d_out, int out_size)
{
    const float* x     = (const float*)d_in[0];
    const float* w_qkv = (const float*)d_in[1];
    const float* b_qkv = (const float*)d_in[2];
    const float* w_out = (const float*)d_in[3];
    const float* b_out = (const float*)d_in[4];
    float* out = (float*)d_out;

    __nv_bfloat16 *xh, *xl, *qh, *ql, *ah, *al, *wqh, *wql, *woh, *wol;
    cudaGetSymbolAddress((void**)&xh, g_xh);
    cudaGetSymbolAddress((void**)&xl, g_xl);
    cudaGetSymbolAddress((void**)&qh, g_qh);
    cudaGetSymbolAddress((void**)&ql, g_ql);
    cudaGetSymbolAddress((void**)&ah, g_ah);
    cudaGetSymbolAddress((void**)&al, g_al);
    cudaGetSymbolAddress((void**)&wqh, g_wqh);
    cudaGetSymbolAddress((void**)&wql, g_wql);
    cudaGetSymbolAddress((void**)&woh, g_woh);
    cudaGetSymbolAddress((void**)&wol, g_wol);

    cudaFuncSetAttribute(gemm_wmma_kernel,
                         cudaFuncAttributeMaxDynamicSharedMemorySize, GEMM_SMEM);
    cudaFuncSetAttribute(flash_attn_mma_kernel,
                         cudaFuncAttributeMaxDynamicSharedMemorySize, FA_SMEM);

    {
        const int nx = S_LEN * D_MODEL;
        split_rows_kernel<<<nx / (256 * 4), 256>>>(x, xh, xl, nx);
        dim3 g1(QKV_COLS / 32, D_MODEL / 32), b1(32, 8);
        transpose_split_kernel<<<g1, b1>>>(w_qkv, wqh, wql, D_MODEL, QKV_COLS);
        dim3 g2(D_MODEL / 32, D_MODEL / 32);
        transpose_split_kernel<<<g2, b1>>>(w_out, woh, wol, D_MODEL, D_MODEL);
    }

    // 1) qkv (bf16 hi/lo) = x @ w_qkv + b_qkv
    {
        dim3 grid(QKV_COLS / 128, S_LEN / 128);
        gemm_wmma_kernel<<<grid, 256, GEMM_SMEM>>>(xh, xl, wqh, wql, b_qkv,
                                                   nullptr, qh, ql, 1,
                                                   S_LEN, QKV_COLS, D_MODEL);
    }
    // 2) attention -> ah/al (bf16 hi/lo)
    {
        dim3 grid(S_LEN / 128, N_HEADS);
        flash_attn_mma_kernel<<<grid, 256, FA_SMEM>>>(qh, ql, ah, al);
    }
    // 3) out = attn @ w_out + b_out (fp32)
    {
        dim3 grid(D_MODEL / 128, S_LEN / 128);
        gemm_wmma_kernel<<<grid, 256, GEMM_SMEM>>>(ah, al, woh, wol, b_out,
                                                   out, nullptr, nullptr, 0,
                                                   S_LEN, D_MODEL, D_MODEL);
    }
}